// round 13
// baseline (speedup 1.0000x reference)
#include <cuda_runtime.h>
#include <math.h>

#define NPTS    32768
#define WIDTH   192
#define COND    64
#define KNN     12
#define NLAYERS 4
#define MIXDIM  390
#define TPL     32            // points per block (proj)

// ---- quantile grid for kNN ----
#define G       16
#define NCELLS  (G*G*G)          // 4096
#define KNB     (NPTS * 4 / 256) // 512 knn blocks (4 threads/query)

// ---- GEMM config: Z(N x 384) = A'(N x 576 bf16) @ B'(576 x 384 bf16)
#define ZN      384
#define KS      36               // k-steps of 16 (576/16)
#define ASTRIDE 196              // u32 stride for A smem rows (bank-safe)
#define BN      128              // block n-tile
#define BCH     (8 * BN)         // u32 per B chunk (8 k-pair rows x 128 cols)

typedef unsigned int  u32;
typedef unsigned short u16;

// ---- scratch (static device allocations; no cudaMalloc allowed) ----
__device__ float  g_Z[NPTS * ZN];            // 50 MB (slot space)
__device__ float  g_hf[NPTS * WIDTH];        // fp32 h (slot space)
__device__ u16    g_hp_hi[NPTS * WIDTH];     // bf16 hi of h (slot space)
__device__ u16    g_hp_lo[NPTS * WIDTH];     // bf16 lo of h (slot space)
__device__ u32    g_wp[NLAYERS * 288 * ZN];  // packed bf16-pair weights
__device__ int    g_knn[NPTS * KNN];         // neighbor SLOTS (slot space)
__device__ float  g_rel[NPTS * 6];           // (slot space)
__device__ float  g_zwpb[WIDTH];
__device__ float  g_gamma[NLAYERS * WIDTH];
__device__ float  g_beta[NLAYERS * WIDTH];

__device__ float  g_bx[G + 1];
__device__ int    g_cnt[NCELLS];
__device__ int    g_cursor[NCELLS];
__device__ int2   g_cell2[NCELLS];
__device__ float4 g_pts[NPTS];               // sorted (x,y,z, orig-idx-as-bits)

// ---- bf16 helpers (hand-rolled, RNE) ----
__device__ __forceinline__ u16 f2bf(float f) {
    u32 b = __float_as_uint(f);
    return (u16)((b + 0x7FFFu + ((b >> 16) & 1u)) >> 16);
}
__device__ __forceinline__ float bf2f(u16 u) {
    return __uint_as_float(((u32)u) << 16);
}

__device__ __forceinline__ int cell_of(float v, const float* bx) {
    int lo = 0;
    if (v >= bx[8])      lo = 8;
    if (v >= bx[lo + 4]) lo += 4;
    if (v >= bx[lo + 2]) lo += 2;
    if (v >= bx[lo + 1]) lo += 1;
    return lo;
}

// B smem swizzle: row 0..7 (k-pair), col 0..127 (n) -> conflict-free
__device__ __forceinline__ int bsw(int row, int col) {
    return row * BN + (col ^ (row * 8));
}

// ============================================================
// Setup: zero grid counters + z-dependent constants + quantiles
// ============================================================
__global__ void setup_kernel(const float* __restrict__ z,
                             const float* __restrict__ Wp, const float* __restrict__ bp,
                             const float* __restrict__ Wg, const float* __restrict__ bg,
                             const float* __restrict__ Wb, const float* __restrict__ bb) {
    int c = threadIdx.x;
    for (int i = c; i < NCELLS; i += blockDim.x) g_cnt[i] = 0;
    if (c <= G) {
        g_bx[c] = (c == 0) ? -1e9f : ((c == G) ? 1e9f
                  : normcdfinvf((float)c / (float)G));
    }
    if (c >= WIDTH) return;
    float s = bp[c];
    for (int k = 0; k < COND; k++)
        s = fmaf(z[k], Wp[(51 + k) * WIDTH + c], s);
    g_zwpb[c] = s;
    for (int li = 0; li < NLAYERS; li++) {
        const float* wg = Wg + li * COND * WIDTH;
        const float* wb = Wb + li * COND * WIDTH;
        float g = bg[li * WIDTH + c];
        float b = bb[li * WIDTH + c];
        for (int k = 0; k < COND; k++) {
            float zk = z[k];
            g = fmaf(zk, wg[k * WIDTH + c], g);
            b = fmaf(zk, wb[k * WIDTH + c], b);
        }
        g_gamma[li * WIDTH + c] = g;
        g_beta[li * WIDTH + c]  = b;
    }
}

// ============================================================
// Weight pack: B' = [Bhi ; Blo ; Bhi] (576 x 384) as bf16 pairs.
// ============================================================
__global__ void wtrans_kernel(const float* __restrict__ Wl) {
    int i  = blockIdx.x;          // u32 row 0..287
    int li = blockIdx.y;
    int n  = threadIdx.x;         // 0..383
    int r  = i / 96;              // region: 0=hi, 1=lo, 2=hi
    int kb = 2 * i - r * 192;     // mix-k base (0..190)
    const float* W = Wl + (size_t)li * MIXDIM * WIDTH;
    int col  = (n < 192) ? n : (n - 192);
    int roff = (n < 192) ? 0 : 192;
    float f0 = W[(roff + kb)     * WIDTH + col];
    float f1 = W[(roff + kb + 1) * WIDTH + col];
    u16 v0, v1;
    if (r == 1) {
        u16 h0 = f2bf(f0), h1 = f2bf(f1);
        v0 = f2bf(f0 - bf2f(h0));
        v1 = f2bf(f1 - bf2f(h1));
    } else {
        v0 = f2bf(f0);
        v1 = f2bf(f1);
    }
    g_wp[(li * 288 + i) * ZN + n] = ((u32)v1 << 16) | (u32)v0;
}

// ============================================================
// Grid build: histogram -> single-block scan -> scatter
// ============================================================
__global__ void hist_kernel(const float* __restrict__ x, int n) {
    int i = blockIdx.x * blockDim.x + threadIdx.x;
    if (i >= n) return;
    const float* bx = g_bx;
    int cx = cell_of(x[i * 3 + 0], bx);
    int cy = cell_of(x[i * 3 + 1], bx);
    int cz = cell_of(x[i * 3 + 2], bx);
    atomicAdd(&g_cnt[(cz * G + cy) * G + cx], 1);
}

__global__ void scan_kernel() {
    __shared__ int sh[1024];
    int t = threadIdx.x;
    int4 v = *reinterpret_cast<const int4*>(&g_cnt[t * 4]);
    int s = v.x + v.y + v.z + v.w;
    sh[t] = s;
    __syncthreads();
    for (int off = 1; off < 1024; off <<= 1) {
        int u = (t >= off) ? sh[t - off] : 0;
        __syncthreads();
        sh[t] += u;
        __syncthreads();
    }
    int ex = sh[t] - s;
    int st0 = ex, st1 = st0 + v.x, st2 = st1 + v.y, st3 = st2 + v.z;
    g_cursor[t * 4 + 0] = st0;  g_cell2[t * 4 + 0] = make_int2(st0, st1);
    g_cursor[t * 4 + 1] = st1;  g_cell2[t * 4 + 1] = make_int2(st1, st2);
    g_cursor[t * 4 + 2] = st2;  g_cell2[t * 4 + 2] = make_int2(st2, st3);
    g_cursor[t * 4 + 3] = st3;  g_cell2[t * 4 + 3] = make_int2(st3, st3 + v.w);
}

__global__ void scatter_kernel(const float* __restrict__ x, int n) {
    int i = blockIdx.x * blockDim.x + threadIdx.x;
    if (i >= n) return;
    const float* bx = g_bx;
    float px = x[i * 3 + 0], py = x[i * 3 + 1], pz = x[i * 3 + 2];
    int cx = cell_of(px, bx), cy = cell_of(py, bx), cz = cell_of(pz, bx);
    int cell = (cz * G + cy) * G + cx;
    int slot = atomicAdd(&g_cursor[cell], 1);
    g_pts[slot] = make_float4(px, py, pz, __int_as_float(i));
}

// ============================================================
// kNN quad: 4 threads per query, candidates split stride-4
// WITHIN each cell; quad-min dmax exchanged after every cell
// (pair-masked shfl, converged trip counts); butterfly merge.
// Outputs in SLOT space.
// ============================================================
__device__ __forceinline__ void knn_quad(int gt, int n, const float* bx) {
    int s   = gt >> 2;
    int sub = gt & 3;
    unsigned pmask = 0xFu << (threadIdx.x & 28);
    if (s >= n) return;
    float4 me = g_pts[s];
    float qx = me.x, qy = me.y, qz = me.z;
    int cx = cell_of(qx, bx), cy = cell_of(qy, bx), cz = cell_of(qz, bx);

    float bd[KNN];
    int   bj[KNN];
#pragma unroll
    for (int r = 0; r < KNN; r++) { bd[r] = 1e30f; bj[r] = 0; }
    float dmax   = 1e30f;     // own subset 12th best
    int   imax   = 0;
    float dprune = 1e30f;     // quad-min, refreshed per cell

    for (int r = 0; r < G; r++) {
        int zlo = max(cz - r, 0), zhi = min(cz + r, G - 1);
        for (int ccz = zlo; ccz <= zhi; ccz++) {
            bool zface = (ccz == cz - r) || (ccz == cz + r);
            float az = fmaxf(fmaxf(bx[ccz] - qz, qz - bx[ccz + 1]), 0.0f);
            int ylo = max(cy - r, 0), yhi = min(cy + r, G - 1);
            for (int ccy = ylo; ccy <= yhi; ccy++) {
                bool face = zface || (ccy == cy - r) || (ccy == cy + r);
                float ay = fmaxf(fmaxf(bx[ccy] - qy, qy - bx[ccy + 1]), 0.0f);
                float ayz = fmaf(ay, ay, az * az);
                int step = face ? 1 : (2 * r);
                for (int dx = -r; dx <= r; dx += step) {
                    int ccx = cx + dx;
                    if (ccx < 0 || ccx >= G) continue;   // uniform across quad
                    float dthr = fminf(dprune, dmax);
                    float ax = fmaxf(fmaxf(bx[ccx] - qx, qx - bx[ccx + 1]), 0.0f);
                    float dmin = fmaf(ax, ax, ayz);
                    if (dmin < dthr) {                   // lane-local; shfl below is outside
                        int2 se = g_cell2[(ccz * G + ccy) * G + ccx];
                        for (int j = se.x + sub; j < se.y; j += 4) {
                            float4 p = g_pts[j];
                            float ddx = p.x - qx, ddy = p.y - qy, ddz = p.z - qz;
                            float d = fmaf(ddx, ddx, fmaf(ddy, ddy, ddz * ddz));
                            if (d < fminf(dprune, dmax) && j != s) {
                                bd[imax] = d;
                                bj[imax] = j;
                                dmax = bd[0]; imax = 0;
#pragma unroll
                                for (int t = 1; t < KNN; t++)
                                    if (bd[t] > dmax) { dmax = bd[t]; imax = t; }
                            }
                        }
                    }
                    // quad-min exchange (all 4 lanes reach here every cell)
                    float t1 = __shfl_xor_sync(pmask, dmax, 1);
                    float m1 = fminf(dmax, t1);
                    float t2 = __shfl_xor_sync(pmask, m1, 2);
                    dprune = fminf(m1, t2);
                }
            }
        }
        // exact stop: min distance from q to complement of searched box
        float f = 1e30f;
        if (cx - r > 0)      f = fminf(f, qx - bx[cx - r]);
        if (cx + r + 1 < G)  f = fminf(f, bx[cx + r + 1] - qx);
        if (cy - r > 0)      f = fminf(f, qy - bx[cy - r]);
        if (cy + r + 1 < G)  f = fminf(f, bx[cy + r + 1] - qy);
        if (cz - r > 0)      f = fminf(f, qz - bx[cz - r]);
        if (cz + r + 1 < G)  f = fminf(f, bx[cz + r + 1] - qz);
        if (f * f >= dprune) break;    // dprune identical across quad
    }

    // butterfly merge: snapshot partner's 12 first (race-free), then insert
#pragma unroll
    for (int st = 1; st <= 2; st <<= 1) {
        float pd[KNN]; int pj[KNN];
#pragma unroll
        for (int t = 0; t < KNN; t++) {
            pd[t] = __shfl_xor_sync(pmask, bd[t], st);
            pj[t] = __shfl_xor_sync(pmask, bj[t], st);
        }
#pragma unroll
        for (int t = 0; t < KNN; t++) {
            if (pd[t] < dmax) {
                bd[imax] = pd[t];
                bj[imax] = pj[t];
                dmax = bd[0]; imax = 0;
#pragma unroll
                for (int u = 1; u < KNN; u++)
                    if (bd[u] > dmax) { dmax = bd[u]; imax = u; }
            }
        }
    }
    if (sub) return;

    // emit slots + rel_feat (single pass: mean & E[r^2]-m^2 std)
    float sx = 0, sy = 0, sz = 0, sxx = 0, syy = 0, szz = 0;
#pragma unroll
    for (int r = 0; r < KNN; r++) {
        int slot = bj[r];
        g_knn[s * KNN + r] = slot;
        float4 p = g_pts[slot];
        float rx = p.x - qx, ry = p.y - qy, rz = p.z - qz;
        sx += rx; sy += ry; sz += rz;
        sxx = fmaf(rx, rx, sxx); syy = fmaf(ry, ry, syy); szz = fmaf(rz, rz, szz);
    }
    const float inv = 1.0f / (float)KNN;
    float mx = sx * inv, my = sy * inv, mz = sz * inv;
    g_rel[s * 6 + 0] = mx;
    g_rel[s * 6 + 1] = my;
    g_rel[s * 6 + 2] = mz;
    g_rel[s * 6 + 3] = sqrtf(fmaxf(sxx * inv - mx * mx, 0.0f));
    g_rel[s * 6 + 4] = sqrtf(fmaxf(syy * inv - my * my, 0.0f));
    g_rel[s * 6 + 5] = sqrtf(fmaxf(szz * inv - mz * mz, 0.0f));
}

// ============================================================
// GEMM device body (R11-proven): 64m x 128n tile, 256 threads,
// 2 m-warps x 4 n-warps, warp m32xn32, swizzled B double-buffer.
// ============================================================
__device__ __forceinline__ void gemm_device(int m0, int n0, const u32* __restrict__ wp,
                                            float* __restrict__ Zout, u32* smem) {
    u32* As = smem;                          // [64][ASTRIDE]
    u32* Bs = smem + 64 * ASTRIDE;           // [2][BCH]
    int tid = threadIdx.x;

    const uint4* hh = reinterpret_cast<const uint4*>(g_hp_hi);  // 24 uint4/row
    const uint4* hl = reinterpret_cast<const uint4*>(g_hp_lo);
    for (int i = tid; i < 64 * 48; i += 256) {
        int row = i / 48, c4 = i % 48;
        uint4 v = (c4 < 24) ? hh[(m0 + row) * 24 + c4]
                            : hl[(m0 + row) * 24 + (c4 - 24)];
        *reinterpret_cast<uint4*>(&As[row * ASTRIDE + c4 * 4]) = v;
    }

    int wid = tid >> 5, lane = tid & 31;
    int mw = wid & 1, nw = wid >> 1;
    int r = lane >> 2, q = lane & 3;

    int brow = tid >> 5;
    int bc4  = lane * 4;
    const u32* bsrc = wp + (size_t)brow * ZN + n0 + bc4;
    int bdst = brow * BN + (bc4 ^ (brow * 8));

    int off0[4], off1[4];
#pragma unroll
    for (int nt = 0; nt < 4; nt++) {
        int nc = nw * 32 + nt * 8 + r;
        off0[nt] = bsw(q, nc);
        off1[nt] = bsw(q + 4, nc);
    }

    float c0[2][4], c1[2][4], c2[2][4], c3[2][4];
#pragma unroll
    for (int mt = 0; mt < 2; mt++)
#pragma unroll
        for (int t = 0; t < 4; t++) {
            c0[mt][t] = 0; c1[mt][t] = 0; c2[mt][t] = 0; c3[mt][t] = 0;
        }

    const u32* arow0 = As + (mw * 32 + r) * ASTRIDE + q;
    const u32* arow1 = arow0 + 8 * ASTRIDE;

    uint4 pref = *reinterpret_cast<const uint4*>(bsrc);
    __syncthreads();

#pragma unroll 2
    for (int ks = 0; ks < KS; ks++) {
        u32* bbuf = Bs + (ks & 1) * BCH;
        *reinterpret_cast<uint4*>(&bbuf[bdst]) = pref;
        __syncthreads();
        if (ks + 1 < KS)
            pref = *reinterpret_cast<const uint4*>(bsrc + (size_t)(ks + 1) * 8 * ZN);

        int acol = (ks < 24) ? (((ks >= 12) ? ks - 12 : ks) * 8)
                             : (96 + (ks - 24) * 8);
        u32 bf0[4], bf1[4];
#pragma unroll
        for (int nt = 0; nt < 4; nt++) {
            bf0[nt] = bbuf[off0[nt]];
            bf1[nt] = bbuf[off1[nt]];
        }
#pragma unroll
        for (int mt = 0; mt < 2; mt++) {
            const u32* ar0 = arow0 + mt * 16 * ASTRIDE;
            const u32* ar1 = arow1 + mt * 16 * ASTRIDE;
            u32 a0 = ar0[acol];
            u32 a1 = ar1[acol];
            u32 a2 = ar0[acol + 4];
            u32 a3 = ar1[acol + 4];
#pragma unroll
            for (int nt = 0; nt < 4; nt++) {
                asm volatile(
                    "mma.sync.aligned.m16n8k16.row.col.f32.bf16.bf16.f32 "
                    "{%0,%1,%2,%3}, {%4,%5,%6,%7}, {%8,%9}, {%0,%1,%2,%3};"
                    : "+f"(c0[mt][nt]), "+f"(c1[mt][nt]), "+f"(c2[mt][nt]), "+f"(c3[mt][nt])
                    : "r"(a0), "r"(a1), "r"(a2), "r"(a3), "r"(bf0[nt]), "r"(bf1[nt]));
            }
        }
    }

#pragma unroll
    for (int mt = 0; mt < 2; mt++) {
#pragma unroll
        for (int nt = 0; nt < 4; nt++) {
            int row = m0 + mw * 32 + mt * 16 + r;
            int col = n0 + nw * 32 + nt * 8 + q * 2;
            *reinterpret_cast<float2*>(&Zout[(size_t)row * ZN + col]) =
                make_float2(c0[mt][nt], c1[mt][nt]);
            *reinterpret_cast<float2*>(&Zout[(size_t)(row + 8) * ZN + col]) =
                make_float2(c2[mt][nt], c3[mt][nt]);
        }
    }
}

// ============================================================
// Fused kernel: blocks [0,KNB) run quad-kNN; rest run GEMM-0.
// ============================================================
__global__ __launch_bounds__(256) void fused0_kernel(const u32* __restrict__ wp,
                                                     float* __restrict__ Zout, int n) {
    extern __shared__ u32 smem[];
    if (blockIdx.x < KNB) {
        __shared__ float bx[G + 1];
        if (threadIdx.x <= G) bx[threadIdx.x] = g_bx[threadIdx.x];
        __syncthreads();
        knn_quad(blockIdx.x * 256 + threadIdx.x, n, bx);
    } else {
        int bid = blockIdx.x - KNB;
        gemm_device((bid & 511) * 64, (bid >> 9) * BN, wp, Zout, smem);
    }
}

__global__ __launch_bounds__(256) void gemm_kernel(const u32* __restrict__ wp,
                                                   float* __restrict__ Zout) {
    extern __shared__ u32 smem[];
    gemm_device(blockIdx.x * 64, blockIdx.y * BN, wp, Zout, smem);
}

// ============================================================
// Projection (slot space): reads g_pts, writes g_hp by slot.
// ============================================================
__global__ __launch_bounds__(192) void proj_kernel(const float* __restrict__ B0,
                                                   const float* __restrict__ B1,
                                                   const float* __restrict__ B2,
                                                   const float* __restrict__ Wp) {
    __shared__ float pe[TPL][52];
    int c    = threadIdx.x;
    int base = blockIdx.x * TPL;

    if (c < TPL) {
        float4 pt = g_pts[base + c];
        float x0 = pt.x, x1 = pt.y, x2 = pt.z;
        const float* Bs[3] = { B0, B1, B2 };
#pragma unroll
        for (int b = 0; b < 3; b++) {
            const float* B = Bs[b];
#pragma unroll
            for (int j = 0; j < 8; j++) {
                float v = fmaf(x0, B[j], fmaf(x1, B[8 + j], x2 * B[16 + j]));
                float sn, cs;
                sincosf(v, &sn, &cs);
                pe[c][b * 16 + j]     = sn;
                pe[c][b * 16 + 8 + j] = cs;
            }
        }
        pe[c][48] = x0; pe[c][49] = x1; pe[c][50] = x2;
    }
    __syncthreads();

    float acc[TPL];
    float zb = g_zwpb[c];
#pragma unroll
    for (int p = 0; p < TPL; p++) acc[p] = zb;
    for (int k = 0; k < 51; k++) {
        float w = Wp[k * WIDTH + c];
#pragma unroll
        for (int p = 0; p < TPL; p++)
            acc[p] = fmaf(pe[p][k], w, acc[p]);
    }
#pragma unroll
    for (int p = 0; p < TPL; p++) {
        float v = acc[p];
        float h = v / (1.0f + expf(-v));
        u16 hi = f2bf(h);
        g_hp_hi[(base + p) * WIDTH + c] = hi;
        g_hp_lo[(base + p) * WIDTH + c] = f2bf(h - bf2f(hi));
    }
}

// ============================================================
// Epilogue (slot space): h' = FiLM(silu(Z1 + mean Z2[nbr] + rel@W3 + b))
// ============================================================
__global__ __launch_bounds__(192) void epi_kernel(const float* __restrict__ Z,
                                                  const float* __restrict__ W3,  // [6][192]
                                                  const float* __restrict__ bl,
                                                  const float* __restrict__ gamma,
                                                  const float* __restrict__ beta) {
    __shared__ int   nidx[TPL * KNN];     // 384
    __shared__ float w3s[6 * WIDTH];
    __shared__ float rels[TPL][6];
    int c    = threadIdx.x;
    int base = blockIdx.x * TPL;

    nidx[c]       = g_knn[base * KNN + c];
    nidx[c + 192] = g_knn[base * KNN + 192 + c];
#pragma unroll
    for (int k = 0; k < 6; k++)
        w3s[k * WIDTH + c] = W3[k * WIDTH + c];
    rels[c / 6][c % 6] = g_rel[base * 6 + c];     // 192 = 32*6
    __syncthreads();

    float bc = bl[c], gc = gamma[c], bt = beta[c];
    float w30 = w3s[c],             w31 = w3s[WIDTH + c],     w32 = w3s[2 * WIDTH + c];
    float w33 = w3s[3 * WIDTH + c], w34 = w3s[4 * WIDTH + c], w35 = w3s[5 * WIDTH + c];

#pragma unroll 2
    for (int p = 0; p < TPL; p++) {
        int m = base + p;
        float z = Z[(size_t)m * ZN + c];
        float s = 0.0f;
#pragma unroll
        for (int j = 0; j < KNN; j++)
            s += Z[(size_t)nidx[p * KNN + j] * ZN + WIDTH + c];
        float rc = rels[p][0] * w30;
        rc = fmaf(rels[p][1], w31, rc);
        rc = fmaf(rels[p][2], w32, rc);
        rc = fmaf(rels[p][3], w33, rc);
        rc = fmaf(rels[p][4], w34, rc);
        rc = fmaf(rels[p][5], w35, rc);
        float v  = z + s * (1.0f / (float)KNN) + rc + bc;
        float sv = v / (1.0f + expf(-v));
        float o  = fmaf(sv, gc, bt);
        g_hf[m * WIDTH + c] = o;
        u16 hi = f2bf(o);
        g_hp_hi[m * WIDTH + c] = hi;
        g_hp_lo[m * WIDTH + c] = f2bf(o - bf2f(hi));
    }
}

// ============================================================
// Output: out[orig] = (h[slot] @ Wout + bout) * 0.01
// ============================================================
__global__ __launch_bounds__(256) void out_kernel(const float* __restrict__ h,
                                                  const float* __restrict__ Wout,
                                                  const float* __restrict__ bout,
                                                  float* __restrict__ out, int n) {
    int s    = (blockIdx.x * blockDim.x + threadIdx.x) >> 5;
    int lane = threadIdx.x & 31;
    if (s >= n) return;
    float o0 = 0, o1 = 0, o2 = 0;
    for (int c = lane; c < WIDTH; c += 32) {
        float hv = h[s * WIDTH + c];
        o0 = fmaf(hv, Wout[c * 3 + 0], o0);
        o1 = fmaf(hv, Wout[c * 3 + 1], o1);
        o2 = fmaf(hv, Wout[c * 3 + 2], o2);
    }
#pragma unroll
    for (int off = 16; off; off >>= 1) {
        o0 += __shfl_down_sync(0xffffffffu, o0, off);
        o1 += __shfl_down_sync(0xffffffffu, o1, off);
        o2 += __shfl_down_sync(0xffffffffu, o2, off);
    }
    if (lane == 0) {
        int qi = __float_as_int(g_pts[s].w);
        out[qi * 3 + 0] = (o0 + bout[0]) * 0.01f;
        out[qi * 3 + 1] = (o1 + bout[1]) * 0.01f;
        out[qi * 3 + 2] = (o2 + bout[2]) * 0.01f;
    }
}

// ============================================================
extern "C" void kernel_launch(void* const* d_in, const int* in_sizes, int n_in,
                              void* d_out, int out_size) {
    const float* x    = (const float*)d_in[0];
    const float* z    = (const float*)d_in[1];
    const float* B0   = (const float*)d_in[2];
    const float* B1   = (const float*)d_in[3];
    const float* B2   = (const float*)d_in[4];
    const float* Wp   = (const float*)d_in[5];
    const float* bp   = (const float*)d_in[6];
    const float* Wl   = (const float*)d_in[7];
    const float* bl   = (const float*)d_in[8];
    const float* Wg   = (const float*)d_in[9];
    const float* bg   = (const float*)d_in[10];
    const float* Wb   = (const float*)d_in[11];
    const float* Wbb  = (const float*)d_in[12];
    const float* Wout = (const float*)d_in[13];
    const float* bout = (const float*)d_in[14];
    float* out = (float*)d_out;

    int n = in_sizes[0] / 3;   // 32768

    float *Zp, *hf, *gma, *bta;
    u32* wp;
    cudaGetSymbolAddress((void**)&Zp,  g_Z);
    cudaGetSymbolAddress((void**)&hf,  g_hf);
    cudaGetSymbolAddress((void**)&gma, g_gamma);
    cudaGetSymbolAddress((void**)&bta, g_beta);
    cudaGetSymbolAddress((void**)&wp,  g_wp);

    const int smem_gemm = (64 * ASTRIDE + 2 * BCH) * (int)sizeof(u32);  // 58368
    cudaFuncSetAttribute(gemm_kernel,   cudaFuncAttributeMaxDynamicSharedMemorySize, smem_gemm);
    cudaFuncSetAttribute(fused0_kernel, cudaFuncAttributeMaxDynamicSharedMemorySize, smem_gemm);

    setup_kernel<<<1, WIDTH>>>(z, Wp, bp, Wg, bg, Wb, Wbb);            // 0
    wtrans_kernel<<<dim3(288, NLAYERS), ZN>>>(Wl);                     // 1
    hist_kernel<<<n / 256, 256>>>(x, n);                               // 2
    scan_kernel<<<1, 1024>>>();                                        // 3 (profiled)
    scatter_kernel<<<n / 256, 256>>>(x, n);                            // 4
    proj_kernel<<<n / TPL, WIDTH>>>(B0, B1, B2, Wp);                   // 5
    fused0_kernel<<<KNB + (n / 64) * (ZN / BN), 256, smem_gemm>>>(wp, Zp, n);  // 6
    epi_kernel<<<n / TPL, WIDTH>>>(Zp, Wl + 384 * WIDTH, bl, gma, bta);        // 7

    for (int li = 1; li < NLAYERS; li++) {
        gemm_kernel<<<dim3(n / 64, ZN / BN), 256, smem_gemm>>>(wp + (size_t)li * 288 * ZN, Zp);
        epi_kernel<<<n / TPL, WIDTH>>>(Zp,
            Wl + (size_t)li * MIXDIM * WIDTH + 384 * WIDTH,
            bl + li * WIDTH, gma + li * WIDTH, bta + li * WIDTH);
    }

    out_kernel<<<(n * 32 + 255) / 256, 256>>>(hf, Wout, bout, out, n);
}

// round 14
// speedup vs baseline: 1.2871x; 1.2871x over previous
#include <cuda_runtime.h>
#include <math.h>

#define NPTS    32768
#define WIDTH   192
#define COND    64
#define KNN     12
#define NLAYERS 4
#define MIXDIM  390
#define TPL     32            // points per block (proj)

// ---- quantile grid for kNN ----
#define G       16
#define NCELLS  (G*G*G)          // 4096
#define KNB     (NPTS / 256)     // 128 knn blocks in fused kernel

// ---- GEMM config: Z(N x 384) = A'(N x 576 bf16) @ B'(576 x 384 bf16)
#define ZN      384
#define KS      36               // k-steps of 16 (576/16)
#define ASTRIDE 196              // u32 stride for A smem rows (bank-safe)
#define BN      128              // block n-tile
#define BCH     (8 * BN)         // u32 per B chunk (8 k-pair rows x 128 cols)

typedef unsigned int  u32;
typedef unsigned short u16;

// ---- scratch (static device allocations; no cudaMalloc allowed) ----
__device__ float  g_Z[NPTS * ZN];            // 50 MB (slot space)
__device__ float  g_hf[NPTS * WIDTH];        // fp32 h (slot space)
__device__ u16    g_hp_hi[NPTS * WIDTH];     // bf16 hi of h (slot space)
__device__ u16    g_hp_lo[NPTS * WIDTH];     // bf16 lo of h (slot space)
__device__ u32    g_wp[NLAYERS * 288 * ZN];  // packed bf16-pair weights
__device__ int    g_knn[NPTS * KNN];         // neighbor SLOTS (slot space)
__device__ float  g_rel[NPTS * 6];           // (slot space)
__device__ float  g_zwpb[WIDTH];
__device__ float  g_gamma[NLAYERS * WIDTH];
__device__ float  g_beta[NLAYERS * WIDTH];

__device__ float  g_bx[G + 1];
__device__ int    g_cnt[NCELLS];
__device__ int    g_cursor[NCELLS];
__device__ int2   g_cell2[NCELLS];
__device__ float4 g_pts[NPTS];               // sorted (x,y,z, orig-idx-as-bits)

// ---- bf16 helpers (hand-rolled, RNE) ----
__device__ __forceinline__ u16 f2bf(float f) {
    u32 b = __float_as_uint(f);
    return (u16)((b + 0x7FFFu + ((b >> 16) & 1u)) >> 16);
}
__device__ __forceinline__ float bf2f(u16 u) {
    return __uint_as_float(((u32)u) << 16);
}

__device__ __forceinline__ int cell_of(float v, const float* bx) {
    int lo = 0;
    if (v >= bx[8])      lo = 8;
    if (v >= bx[lo + 4]) lo += 4;
    if (v >= bx[lo + 2]) lo += 2;
    if (v >= bx[lo + 1]) lo += 1;
    return lo;
}

// B smem swizzle: row 0..7 (k-pair), col 0..127 (n) -> conflict-free
__device__ __forceinline__ int bsw(int row, int col) {
    return row * BN + (col ^ (row * 8));
}

// ============================================================
// Setup: zero grid counters + z-dependent constants + quantiles
// ============================================================
__global__ void setup_kernel(const float* __restrict__ z,
                             const float* __restrict__ Wp, const float* __restrict__ bp,
                             const float* __restrict__ Wg, const float* __restrict__ bg,
                             const float* __restrict__ Wb, const float* __restrict__ bb) {
    int c = threadIdx.x;
    for (int i = c; i < NCELLS; i += blockDim.x) g_cnt[i] = 0;
    if (c <= G) {
        g_bx[c] = (c == 0) ? -1e9f : ((c == G) ? 1e9f
                  : normcdfinvf((float)c / (float)G));
    }
    if (c >= WIDTH) return;
    float s = bp[c];
    for (int k = 0; k < COND; k++)
        s = fmaf(z[k], Wp[(51 + k) * WIDTH + c], s);
    g_zwpb[c] = s;
    for (int li = 0; li < NLAYERS; li++) {
        const float* wg = Wg + li * COND * WIDTH;
        const float* wb = Wb + li * COND * WIDTH;
        float g = bg[li * WIDTH + c];
        float b = bb[li * WIDTH + c];
        for (int k = 0; k < COND; k++) {
            float zk = z[k];
            g = fmaf(zk, wg[k * WIDTH + c], g);
            b = fmaf(zk, wb[k * WIDTH + c], b);
        }
        g_gamma[li * WIDTH + c] = g;
        g_beta[li * WIDTH + c]  = b;
    }
}

// ============================================================
// Weight pack: B' = [Bhi ; Blo ; Bhi] (576 x 384) as bf16 pairs.
// ============================================================
__global__ void wtrans_kernel(const float* __restrict__ Wl) {
    int i  = blockIdx.x;          // u32 row 0..287
    int li = blockIdx.y;
    int n  = threadIdx.x;         // 0..383
    int r  = i / 96;              // region: 0=hi, 1=lo, 2=hi
    int kb = 2 * i - r * 192;     // mix-k base (0..190)
    const float* W = Wl + (size_t)li * MIXDIM * WIDTH;
    int col  = (n < 192) ? n : (n - 192);
    int roff = (n < 192) ? 0 : 192;
    float f0 = W[(roff + kb)     * WIDTH + col];
    float f1 = W[(roff + kb + 1) * WIDTH + col];
    u16 v0, v1;
    if (r == 1) {
        u16 h0 = f2bf(f0), h1 = f2bf(f1);
        v0 = f2bf(f0 - bf2f(h0));
        v1 = f2bf(f1 - bf2f(h1));
    } else {
        v0 = f2bf(f0);
        v1 = f2bf(f1);
    }
    g_wp[(li * 288 + i) * ZN + n] = ((u32)v1 << 16) | (u32)v0;
}

// ============================================================
// Grid build: histogram -> single-block scan -> scatter
// ============================================================
__global__ void hist_kernel(const float* __restrict__ x, int n) {
    int i = blockIdx.x * blockDim.x + threadIdx.x;
    if (i >= n) return;
    const float* bx = g_bx;
    int cx = cell_of(x[i * 3 + 0], bx);
    int cy = cell_of(x[i * 3 + 1], bx);
    int cz = cell_of(x[i * 3 + 2], bx);
    atomicAdd(&g_cnt[(cz * G + cy) * G + cx], 1);
}

__global__ void scan_kernel() {
    __shared__ int sh[1024];
    int t = threadIdx.x;
    int4 v = *reinterpret_cast<const int4*>(&g_cnt[t * 4]);
    int s = v.x + v.y + v.z + v.w;
    sh[t] = s;
    __syncthreads();
    for (int off = 1; off < 1024; off <<= 1) {
        int u = (t >= off) ? sh[t - off] : 0;
        __syncthreads();
        sh[t] += u;
        __syncthreads();
    }
    int ex = sh[t] - s;
    int st0 = ex, st1 = st0 + v.x, st2 = st1 + v.y, st3 = st2 + v.z;
    g_cursor[t * 4 + 0] = st0;  g_cell2[t * 4 + 0] = make_int2(st0, st1);
    g_cursor[t * 4 + 1] = st1;  g_cell2[t * 4 + 1] = make_int2(st1, st2);
    g_cursor[t * 4 + 2] = st2;  g_cell2[t * 4 + 2] = make_int2(st2, st3);
    g_cursor[t * 4 + 3] = st3;  g_cell2[t * 4 + 3] = make_int2(st3, st3 + v.w);
}

__global__ void scatter_kernel(const float* __restrict__ x, int n) {
    int i = blockIdx.x * blockDim.x + threadIdx.x;
    if (i >= n) return;
    const float* bx = g_bx;
    float px = x[i * 3 + 0], py = x[i * 3 + 1], pz = x[i * 3 + 2];
    int cx = cell_of(px, bx), cy = cell_of(py, bx), cz = cell_of(pz, bx);
    int cell = (cz * G + cy) * G + cx;
    int slot = atomicAdd(&g_cursor[cell], 1);
    g_pts[slot] = make_float4(px, py, pz, __int_as_float(i));
}

// ============================================================
// kNN device body: one thread per sorted point; outputs in
// SLOT space (g_knn holds neighbor slots, g_rel by slot).
// ============================================================
__device__ __noinline__ void knn_device(int s, int n, const float* bx) {
    if (s >= n) return;
    float4 me = g_pts[s];
    float qx = me.x, qy = me.y, qz = me.z;
    int cx = cell_of(qx, bx), cy = cell_of(qy, bx), cz = cell_of(qz, bx);

    float bd[KNN];
    int   bj[KNN];
#pragma unroll
    for (int r = 0; r < KNN; r++) { bd[r] = 1e30f; bj[r] = 0; }
    float dmax = 1e30f;
    int   imax = 0;

    for (int r = 0; r < G; r++) {
        int zlo = max(cz - r, 0), zhi = min(cz + r, G - 1);
        for (int ccz = zlo; ccz <= zhi; ccz++) {
            bool zface = (ccz == cz - r) || (ccz == cz + r);
            float az = fmaxf(fmaxf(bx[ccz] - qz, qz - bx[ccz + 1]), 0.0f);
            int ylo = max(cy - r, 0), yhi = min(cy + r, G - 1);
            for (int ccy = ylo; ccy <= yhi; ccy++) {
                bool face = zface || (ccy == cy - r) || (ccy == cy + r);
                float ay = fmaxf(fmaxf(bx[ccy] - qy, qy - bx[ccy + 1]), 0.0f);
                float ayz = fmaf(ay, ay, az * az);
                if (ayz >= dmax) continue;
                int step = face ? 1 : (2 * r);
                for (int dx = -r; dx <= r; dx += step) {
                    int ccx = cx + dx;
                    if (ccx < 0 || ccx >= G) continue;
                    float ax = fmaxf(fmaxf(bx[ccx] - qx, qx - bx[ccx + 1]), 0.0f);
                    float dmin = fmaf(ax, ax, ayz);
                    if (dmin >= dmax) continue;
                    int2 se = g_cell2[(ccz * G + ccy) * G + ccx];
                    for (int j = se.x; j < se.y; j++) {
                        float4 p = g_pts[j];
                        float ddx = p.x - qx, ddy = p.y - qy, ddz = p.z - qz;
                        float d = fmaf(ddx, ddx, fmaf(ddy, ddy, ddz * ddz));
                        if (d < dmax && j != s) {
                            bd[imax] = d;
                            bj[imax] = j;
                            dmax = bd[0]; imax = 0;
#pragma unroll
                            for (int t = 1; t < KNN; t++)
                                if (bd[t] > dmax) { dmax = bd[t]; imax = t; }
                        }
                    }
                }
            }
        }
        float f = 1e30f;
        if (cx - r > 0)      f = fminf(f, qx - bx[cx - r]);
        if (cx + r + 1 < G)  f = fminf(f, bx[cx + r + 1] - qx);
        if (cy - r > 0)      f = fminf(f, qy - bx[cy - r]);
        if (cy + r + 1 < G)  f = fminf(f, bx[cy + r + 1] - qy);
        if (cz - r > 0)      f = fminf(f, qz - bx[cz - r]);
        if (cz + r + 1 < G)  f = fminf(f, bx[cz + r + 1] - qz);
        if (f * f >= dmax) break;
    }

    float sx = 0, sy = 0, sz = 0, sxx = 0, syy = 0, szz = 0;
#pragma unroll
    for (int r = 0; r < KNN; r++) {
        int slot = bj[r];
        g_knn[s * KNN + r] = slot;           // SLOT index
        float4 p = g_pts[slot];
        float rx = p.x - qx, ry = p.y - qy, rz = p.z - qz;
        sx += rx; sy += ry; sz += rz;
        sxx = fmaf(rx, rx, sxx); syy = fmaf(ry, ry, syy); szz = fmaf(rz, rz, szz);
    }
    const float inv = 1.0f / (float)KNN;
    float mx = sx * inv, my = sy * inv, mz = sz * inv;
    g_rel[s * 6 + 0] = mx;
    g_rel[s * 6 + 1] = my;
    g_rel[s * 6 + 2] = mz;
    g_rel[s * 6 + 3] = sqrtf(fmaxf(sxx * inv - mx * mx, 0.0f));
    g_rel[s * 6 + 4] = sqrtf(fmaxf(syy * inv - my * my, 0.0f));
    g_rel[s * 6 + 5] = sqrtf(fmaxf(szz * inv - mz * mz, 0.0f));
}

// ============================================================
// GEMM device body (R11-proven): 64m x 128n tile, 256 threads,
// 2 m-warps x 4 n-warps, warp m32xn32, swizzled B double-buffer.
// ============================================================
__device__ __forceinline__ void gemm_device(int m0, int n0, const u32* __restrict__ wp,
                                            float* __restrict__ Zout, u32* smem) {
    u32* As = smem;                          // [64][ASTRIDE]
    u32* Bs = smem + 64 * ASTRIDE;           // [2][BCH]
    int tid = threadIdx.x;

    const uint4* hh = reinterpret_cast<const uint4*>(g_hp_hi);  // 24 uint4/row
    const uint4* hl = reinterpret_cast<const uint4*>(g_hp_lo);
    for (int i = tid; i < 64 * 48; i += 256) {
        int row = i / 48, c4 = i % 48;
        uint4 v = (c4 < 24) ? hh[(m0 + row) * 24 + c4]
                            : hl[(m0 + row) * 24 + (c4 - 24)];
        *reinterpret_cast<uint4*>(&As[row * ASTRIDE + c4 * 4]) = v;
    }

    int wid = tid >> 5, lane = tid & 31;
    int mw = wid & 1, nw = wid >> 1;
    int r = lane >> 2, q = lane & 3;

    int brow = tid >> 5;
    int bc4  = lane * 4;
    const u32* bsrc = wp + (size_t)brow * ZN + n0 + bc4;
    int bdst = brow * BN + (bc4 ^ (brow * 8));

    int off0[4], off1[4];
#pragma unroll
    for (int nt = 0; nt < 4; nt++) {
        int nc = nw * 32 + nt * 8 + r;
        off0[nt] = bsw(q, nc);
        off1[nt] = bsw(q + 4, nc);
    }

    float c0[2][4], c1[2][4], c2[2][4], c3[2][4];
#pragma unroll
    for (int mt = 0; mt < 2; mt++)
#pragma unroll
        for (int t = 0; t < 4; t++) {
            c0[mt][t] = 0; c1[mt][t] = 0; c2[mt][t] = 0; c3[mt][t] = 0;
        }

    const u32* arow0 = As + (mw * 32 + r) * ASTRIDE + q;
    const u32* arow1 = arow0 + 8 * ASTRIDE;

    uint4 pref = *reinterpret_cast<const uint4*>(bsrc);
    __syncthreads();

#pragma unroll 2
    for (int ks = 0; ks < KS; ks++) {
        u32* bbuf = Bs + (ks & 1) * BCH;
        *reinterpret_cast<uint4*>(&bbuf[bdst]) = pref;
        __syncthreads();
        if (ks + 1 < KS)
            pref = *reinterpret_cast<const uint4*>(bsrc + (size_t)(ks + 1) * 8 * ZN);

        int acol = (ks < 24) ? (((ks >= 12) ? ks - 12 : ks) * 8)
                             : (96 + (ks - 24) * 8);
        u32 bf0[4], bf1[4];
#pragma unroll
        for (int nt = 0; nt < 4; nt++) {
            bf0[nt] = bbuf[off0[nt]];
            bf1[nt] = bbuf[off1[nt]];
        }
#pragma unroll
        for (int mt = 0; mt < 2; mt++) {
            const u32* ar0 = arow0 + mt * 16 * ASTRIDE;
            const u32* ar1 = arow1 + mt * 16 * ASTRIDE;
            u32 a0 = ar0[acol];
            u32 a1 = ar1[acol];
            u32 a2 = ar0[acol + 4];
            u32 a3 = ar1[acol + 4];
#pragma unroll
            for (int nt = 0; nt < 4; nt++) {
                asm volatile(
                    "mma.sync.aligned.m16n8k16.row.col.f32.bf16.bf16.f32 "
                    "{%0,%1,%2,%3}, {%4,%5,%6,%7}, {%8,%9}, {%0,%1,%2,%3};"
                    : "+f"(c0[mt][nt]), "+f"(c1[mt][nt]), "+f"(c2[mt][nt]), "+f"(c3[mt][nt])
                    : "r"(a0), "r"(a1), "r"(a2), "r"(a3), "r"(bf0[nt]), "r"(bf1[nt]));
            }
        }
    }

#pragma unroll
    for (int mt = 0; mt < 2; mt++) {
#pragma unroll
        for (int nt = 0; nt < 4; nt++) {
            int row = m0 + mw * 32 + mt * 16 + r;
            int col = n0 + nw * 32 + nt * 8 + q * 2;
            *reinterpret_cast<float2*>(&Zout[(size_t)row * ZN + col]) =
                make_float2(c0[mt][nt], c1[mt][nt]);
            *reinterpret_cast<float2*>(&Zout[(size_t)(row + 8) * ZN + col]) =
                make_float2(c2[mt][nt], c3[mt][nt]);
        }
    }
}

// ============================================================
// Fused kernel: blocks [0,KNB) run kNN; the rest run GEMM-0.
// ============================================================
__global__ __launch_bounds__(256) void fused0_kernel(const u32* __restrict__ wp,
                                                     float* __restrict__ Zout, int n) {
    extern __shared__ u32 smem[];
    if (blockIdx.x < KNB) {
        __shared__ float bx[G + 1];
        if (threadIdx.x <= G) bx[threadIdx.x] = g_bx[threadIdx.x];
        __syncthreads();
        knn_device(blockIdx.x * 256 + threadIdx.x, n, bx);
    } else {
        int bid = blockIdx.x - KNB;
        gemm_device((bid & 511) * 64, (bid >> 9) * BN, wp, Zout, smem);
    }
}

__global__ __launch_bounds__(256) void gemm_kernel(const u32* __restrict__ wp,
                                                   float* __restrict__ Zout) {
    extern __shared__ u32 smem[];
    gemm_device(blockIdx.x * 64, blockIdx.y * BN, wp, Zout, smem);
}

// ============================================================
// Projection (slot space): reads g_pts, writes g_hp by slot.
// ============================================================
__global__ __launch_bounds__(192) void proj_kernel(const float* __restrict__ B0,
                                                   const float* __restrict__ B1,
                                                   const float* __restrict__ B2,
                                                   const float* __restrict__ Wp) {
    __shared__ float pe[TPL][52];
    int c    = threadIdx.x;
    int base = blockIdx.x * TPL;

    if (c < TPL) {
        float4 pt = g_pts[base + c];
        float x0 = pt.x, x1 = pt.y, x2 = pt.z;
        const float* Bs[3] = { B0, B1, B2 };
#pragma unroll
        for (int b = 0; b < 3; b++) {
            const float* B = Bs[b];
#pragma unroll
            for (int j = 0; j < 8; j++) {
                float v = fmaf(x0, B[j], fmaf(x1, B[8 + j], x2 * B[16 + j]));
                float sn, cs;
                sincosf(v, &sn, &cs);
                pe[c][b * 16 + j]     = sn;
                pe[c][b * 16 + 8 + j] = cs;
            }
        }
        pe[c][48] = x0; pe[c][49] = x1; pe[c][50] = x2;
    }
    __syncthreads();

    float acc[TPL];
    float zb = g_zwpb[c];
#pragma unroll
    for (int p = 0; p < TPL; p++) acc[p] = zb;
    for (int k = 0; k < 51; k++) {
        float w = Wp[k * WIDTH + c];
#pragma unroll
        for (int p = 0; p < TPL; p++)
            acc[p] = fmaf(pe[p][k], w, acc[p]);
    }
#pragma unroll
    for (int p = 0; p < TPL; p++) {
        float v = acc[p];
        float h = v / (1.0f + expf(-v));
        u16 hi = f2bf(h);
        g_hp_hi[(base + p) * WIDTH + c] = hi;
        g_hp_lo[(base + p) * WIDTH + c] = f2bf(h - bf2f(hi));
    }
}

// ============================================================
// Epilogue (slot space): h' = FiLM(silu(Z1 + mean Z2[nbr] + rel@W3 + b))
// flags: bit0 = write g_hf (last layer), bit1 = write g_hp (non-last)
// ============================================================
__global__ __launch_bounds__(192) void epi_kernel(const float* __restrict__ Z,
                                                  const float* __restrict__ W3,  // [6][192]
                                                  const float* __restrict__ bl,
                                                  const float* __restrict__ gamma,
                                                  const float* __restrict__ beta,
                                                  int flags) {
    __shared__ int   nidx[TPL * KNN];     // 384
    __shared__ float w3s[6 * WIDTH];
    __shared__ float rels[TPL][6];
    int c    = threadIdx.x;
    int base = blockIdx.x * TPL;

    nidx[c]       = g_knn[base * KNN + c];
    nidx[c + 192] = g_knn[base * KNN + 192 + c];
#pragma unroll
    for (int k = 0; k < 6; k++)
        w3s[k * WIDTH + c] = W3[k * WIDTH + c];
    rels[c / 6][c % 6] = g_rel[base * 6 + c];     // 192 = 32*6
    __syncthreads();

    float bc = bl[c], gc = gamma[c], bt = beta[c];
    float w30 = w3s[c],             w31 = w3s[WIDTH + c],     w32 = w3s[2 * WIDTH + c];
    float w33 = w3s[3 * WIDTH + c], w34 = w3s[4 * WIDTH + c], w35 = w3s[5 * WIDTH + c];
    bool whf = (flags & 1) != 0;
    bool whp = (flags & 2) != 0;

#pragma unroll 2
    for (int p = 0; p < TPL; p++) {
        int m = base + p;
        float z = Z[(size_t)m * ZN + c];
        float s = 0.0f;
#pragma unroll
        for (int j = 0; j < KNN; j++)
            s += Z[(size_t)nidx[p * KNN + j] * ZN + WIDTH + c];
        float rc = rels[p][0] * w30;
        rc = fmaf(rels[p][1], w31, rc);
        rc = fmaf(rels[p][2], w32, rc);
        rc = fmaf(rels[p][3], w33, rc);
        rc = fmaf(rels[p][4], w34, rc);
        rc = fmaf(rels[p][5], w35, rc);
        float v  = z + s * (1.0f / (float)KNN) + rc + bc;
        float sv = v / (1.0f + expf(-v));
        float o  = fmaf(sv, gc, bt);
        if (whf)
            g_hf[m * WIDTH + c] = o;
        if (whp) {
            u16 hi = f2bf(o);
            g_hp_hi[m * WIDTH + c] = hi;
            g_hp_lo[m * WIDTH + c] = f2bf(o - bf2f(hi));
        }
    }
}

// ============================================================
// Output: out[orig] = (h[slot] @ Wout + bout) * 0.01
// ============================================================
__global__ __launch_bounds__(256) void out_kernel(const float* __restrict__ h,
                                                  const float* __restrict__ Wout,
                                                  const float* __restrict__ bout,
                                                  float* __restrict__ out, int n) {
    int s    = (blockIdx.x * blockDim.x + threadIdx.x) >> 5;
    int lane = threadIdx.x & 31;
    if (s >= n) return;
    float o0 = 0, o1 = 0, o2 = 0;
    for (int c = lane; c < WIDTH; c += 32) {
        float hv = h[s * WIDTH + c];
        o0 = fmaf(hv, Wout[c * 3 + 0], o0);
        o1 = fmaf(hv, Wout[c * 3 + 1], o1);
        o2 = fmaf(hv, Wout[c * 3 + 2], o2);
    }
#pragma unroll
    for (int off = 16; off; off >>= 1) {
        o0 += __shfl_down_sync(0xffffffffu, o0, off);
        o1 += __shfl_down_sync(0xffffffffu, o1, off);
        o2 += __shfl_down_sync(0xffffffffu, o2, off);
    }
    if (lane == 0) {
        int qi = __float_as_int(g_pts[s].w);
        out[qi * 3 + 0] = (o0 + bout[0]) * 0.01f;
        out[qi * 3 + 1] = (o1 + bout[1]) * 0.01f;
        out[qi * 3 + 2] = (o2 + bout[2]) * 0.01f;
    }
}

// ============================================================
extern "C" void kernel_launch(void* const* d_in, const int* in_sizes, int n_in,
                              void* d_out, int out_size) {
    const float* x    = (const float*)d_in[0];
    const float* z    = (const float*)d_in[1];
    const float* B0   = (const float*)d_in[2];
    const float* B1   = (const float*)d_in[3];
    const float* B2   = (const float*)d_in[4];
    const float* Wp   = (const float*)d_in[5];
    const float* bp   = (const float*)d_in[6];
    const float* Wl   = (const float*)d_in[7];
    const float* bl   = (const float*)d_in[8];
    const float* Wg   = (const float*)d_in[9];
    const float* bg   = (const float*)d_in[10];
    const float* Wb   = (const float*)d_in[11];
    const float* Wbb  = (const float*)d_in[12];
    const float* Wout = (const float*)d_in[13];
    const float* bout = (const float*)d_in[14];
    float* out = (float*)d_out;

    int n = in_sizes[0] / 3;   // 32768

    float *Zp, *hf, *gma, *bta;
    u32* wp;
    cudaGetSymbolAddress((void**)&Zp,  g_Z);
    cudaGetSymbolAddress((void**)&hf,  g_hf);
    cudaGetSymbolAddress((void**)&gma, g_gamma);
    cudaGetSymbolAddress((void**)&bta, g_beta);
    cudaGetSymbolAddress((void**)&wp,  g_wp);

    const int smem_gemm = (64 * ASTRIDE + 2 * BCH) * (int)sizeof(u32);  // 58368
    cudaFuncSetAttribute(gemm_kernel,   cudaFuncAttributeMaxDynamicSharedMemorySize, smem_gemm);
    cudaFuncSetAttribute(fused0_kernel, cudaFuncAttributeMaxDynamicSharedMemorySize, smem_gemm);

    setup_kernel<<<1, WIDTH>>>(z, Wp, bp, Wg, bg, Wb, Wbb);            // 0
    wtrans_kernel<<<dim3(288, NLAYERS), ZN>>>(Wl);                     // 1
    hist_kernel<<<n / 256, 256>>>(x, n);                               // 2
    scan_kernel<<<1, 1024>>>();                                        // 3 (profiled)
    scatter_kernel<<<n / 256, 256>>>(x, n);                            // 4
    proj_kernel<<<n / TPL, WIDTH>>>(B0, B1, B2, Wp);                   // 5
    fused0_kernel<<<KNB + (n / 64) * (ZN / BN), 256, smem_gemm>>>(wp, Zp, n);  // 6
    epi_kernel<<<n / TPL, WIDTH>>>(Zp, Wl + 384 * WIDTH, bl, gma, bta, 2);     // 7

    for (int li = 1; li < NLAYERS; li++) {
        gemm_kernel<<<dim3(n / 64, ZN / BN), 256, smem_gemm>>>(wp + (size_t)li * 288 * ZN, Zp);
        epi_kernel<<<n / TPL, WIDTH>>>(Zp,
            Wl + (size_t)li * MIXDIM * WIDTH + 384 * WIDTH,
            bl + li * WIDTH, gma + li * WIDTH, bta + li * WIDTH,
            (li == NLAYERS - 1) ? 1 : 2);
    }

    out_kernel<<<(n * 32 + 255) / 256, 256>>>(hf, Wout, bout, out, n);
}

// round 15
// speedup vs baseline: 1.3548x; 1.0526x over previous
#include <cuda_runtime.h>
#include <math.h>

#define NPTS    32768
#define WIDTH   192
#define COND    64
#define KNN     12
#define NLAYERS 4
#define MIXDIM  390
#define TPL     32            // points per block (proj)

// ---- quantile grid for kNN ----
#define G       16
#define NCELLS  (G*G*G)          // 4096
#define KNB     (NPTS / 256)     // 128 knn blocks in fused kernel

// ---- GEMM config: Z(N x 384) = A'(N x 576 bf16) @ B'(576 x 384 bf16)
#define ZN      384
#define KS      36               // k-steps of 16 (576/16)
#define ASTRIDE 196              // u32 stride for A smem rows (bank-safe)
#define BN      128              // block n-tile
#define BCH     (8 * BN)         // u32 per B chunk (8 k-pair rows x 128 cols)

typedef unsigned int  u32;
typedef unsigned short u16;

// ---- scratch (static device allocations; no cudaMalloc allowed) ----
__device__ float  g_Z[NPTS * ZN];            // 50 MB (slot space)
__device__ float  g_hf[NPTS * WIDTH];        // fp32 h (slot space)
__device__ u16    g_hp_hi[NPTS * WIDTH];     // bf16 hi of h (slot space)
__device__ u16    g_hp_lo[NPTS * WIDTH];     // bf16 lo of h (slot space)
__device__ u32    g_wp[NLAYERS * 288 * ZN];  // packed bf16-pair weights
__device__ int    g_knn[NPTS * KNN];         // neighbor SLOTS (slot space)
__device__ float  g_rel[NPTS * 6];           // (slot space)
__device__ float  g_zwpb[WIDTH];
__device__ float  g_gamma[NLAYERS * WIDTH];
__device__ float  g_beta[NLAYERS * WIDTH];

__device__ float  g_bx[G + 1];
__device__ int    g_cnt[NCELLS];
__device__ int    g_cursor[NCELLS];
__device__ int2   g_cell2[NCELLS];
__device__ float4 g_pts[NPTS];               // sorted (x,y,z, orig-idx-as-bits)

// ---- bf16 helpers (hand-rolled, RNE) ----
__device__ __forceinline__ u16 f2bf(float f) {
    u32 b = __float_as_uint(f);
    return (u16)((b + 0x7FFFu + ((b >> 16) & 1u)) >> 16);
}
__device__ __forceinline__ float bf2f(u16 u) {
    return __uint_as_float(((u32)u) << 16);
}

__device__ __forceinline__ int cell_of(float v, const float* bx) {
    int lo = 0;
    if (v >= bx[8])      lo = 8;
    if (v >= bx[lo + 4]) lo += 4;
    if (v >= bx[lo + 2]) lo += 2;
    if (v >= bx[lo + 1]) lo += 1;
    return lo;
}

// B smem swizzle: row 0..7 (k-pair), col 0..127 (n) -> conflict-free
__device__ __forceinline__ int bsw(int row, int col) {
    return row * BN + (col ^ (row * 8));
}

// ============================================================
// Setup: zero grid counters + z-dependent constants + quantiles
// ============================================================
__global__ void setup_kernel(const float* __restrict__ z,
                             const float* __restrict__ Wp, const float* __restrict__ bp,
                             const float* __restrict__ Wg, const float* __restrict__ bg,
                             const float* __restrict__ Wb, const float* __restrict__ bb) {
    int c = threadIdx.x;
    for (int i = c; i < NCELLS; i += blockDim.x) g_cnt[i] = 0;
    if (c <= G) {
        g_bx[c] = (c == 0) ? -1e9f : ((c == G) ? 1e9f
                  : normcdfinvf((float)c / (float)G));
    }
    if (c >= WIDTH) return;
    float s = bp[c];
    for (int k = 0; k < COND; k++)
        s = fmaf(z[k], Wp[(51 + k) * WIDTH + c], s);
    g_zwpb[c] = s;
    for (int li = 0; li < NLAYERS; li++) {
        const float* wg = Wg + li * COND * WIDTH;
        const float* wb = Wb + li * COND * WIDTH;
        float g = bg[li * WIDTH + c];
        float b = bb[li * WIDTH + c];
        for (int k = 0; k < COND; k++) {
            float zk = z[k];
            g = fmaf(zk, wg[k * WIDTH + c], g);
            b = fmaf(zk, wb[k * WIDTH + c], b);
        }
        g_gamma[li * WIDTH + c] = g;
        g_beta[li * WIDTH + c]  = b;
    }
}

// ============================================================
// Weight pack: B' = [Bhi ; Blo ; Bhi] (576 x 384) as bf16 pairs.
// ============================================================
__global__ void wtrans_kernel(const float* __restrict__ Wl) {
    int i  = blockIdx.x;          // u32 row 0..287
    int li = blockIdx.y;
    int n  = threadIdx.x;         // 0..383
    int r  = i / 96;              // region: 0=hi, 1=lo, 2=hi
    int kb = 2 * i - r * 192;     // mix-k base (0..190)
    const float* W = Wl + (size_t)li * MIXDIM * WIDTH;
    int col  = (n < 192) ? n : (n - 192);
    int roff = (n < 192) ? 0 : 192;
    float f0 = W[(roff + kb)     * WIDTH + col];
    float f1 = W[(roff + kb + 1) * WIDTH + col];
    u16 v0, v1;
    if (r == 1) {
        u16 h0 = f2bf(f0), h1 = f2bf(f1);
        v0 = f2bf(f0 - bf2f(h0));
        v1 = f2bf(f1 - bf2f(h1));
    } else {
        v0 = f2bf(f0);
        v1 = f2bf(f1);
    }
    g_wp[(li * 288 + i) * ZN + n] = ((u32)v1 << 16) | (u32)v0;
}

// ============================================================
// Grid build: histogram -> single-block scan -> scatter
// ============================================================
__global__ void hist_kernel(const float* __restrict__ x, int n) {
    int i = blockIdx.x * blockDim.x + threadIdx.x;
    if (i >= n) return;
    const float* bx = g_bx;
    int cx = cell_of(x[i * 3 + 0], bx);
    int cy = cell_of(x[i * 3 + 1], bx);
    int cz = cell_of(x[i * 3 + 2], bx);
    atomicAdd(&g_cnt[(cz * G + cy) * G + cx], 1);
}

__global__ void scan_kernel() {
    __shared__ int sh[1024];
    int t = threadIdx.x;
    int4 v = *reinterpret_cast<const int4*>(&g_cnt[t * 4]);
    int s = v.x + v.y + v.z + v.w;
    sh[t] = s;
    __syncthreads();
    for (int off = 1; off < 1024; off <<= 1) {
        int u = (t >= off) ? sh[t - off] : 0;
        __syncthreads();
        sh[t] += u;
        __syncthreads();
    }
    int ex = sh[t] - s;
    int st0 = ex, st1 = st0 + v.x, st2 = st1 + v.y, st3 = st2 + v.z;
    g_cursor[t * 4 + 0] = st0;  g_cell2[t * 4 + 0] = make_int2(st0, st1);
    g_cursor[t * 4 + 1] = st1;  g_cell2[t * 4 + 1] = make_int2(st1, st2);
    g_cursor[t * 4 + 2] = st2;  g_cell2[t * 4 + 2] = make_int2(st2, st3);
    g_cursor[t * 4 + 3] = st3;  g_cell2[t * 4 + 3] = make_int2(st3, st3 + v.w);
}

__global__ void scatter_kernel(const float* __restrict__ x, int n) {
    int i = blockIdx.x * blockDim.x + threadIdx.x;
    if (i >= n) return;
    const float* bx = g_bx;
    float px = x[i * 3 + 0], py = x[i * 3 + 1], pz = x[i * 3 + 2];
    int cx = cell_of(px, bx), cy = cell_of(py, bx), cz = cell_of(pz, bx);
    int cell = (cz * G + cy) * G + cx;
    int slot = atomicAdd(&g_cursor[cell], 1);
    g_pts[slot] = make_float4(px, py, pz, __int_as_float(i));
}

// ============================================================
// kNN device body: one thread per sorted point; outputs in
// SLOT space (g_knn holds neighbor slots, g_rel by slot).
// ============================================================
__device__ __noinline__ void knn_device(int s, int n, const float* bx) {
    if (s >= n) return;
    float4 me = g_pts[s];
    float qx = me.x, qy = me.y, qz = me.z;
    int cx = cell_of(qx, bx), cy = cell_of(qy, bx), cz = cell_of(qz, bx);

    float bd[KNN];
    int   bj[KNN];
#pragma unroll
    for (int r = 0; r < KNN; r++) { bd[r] = 1e30f; bj[r] = 0; }
    float dmax = 1e30f;
    int   imax = 0;

    for (int r = 0; r < G; r++) {
        int zlo = max(cz - r, 0), zhi = min(cz + r, G - 1);
        for (int ccz = zlo; ccz <= zhi; ccz++) {
            bool zface = (ccz == cz - r) || (ccz == cz + r);
            float az = fmaxf(fmaxf(bx[ccz] - qz, qz - bx[ccz + 1]), 0.0f);
            int ylo = max(cy - r, 0), yhi = min(cy + r, G - 1);
            for (int ccy = ylo; ccy <= yhi; ccy++) {
                bool face = zface || (ccy == cy - r) || (ccy == cy + r);
                float ay = fmaxf(fmaxf(bx[ccy] - qy, qy - bx[ccy + 1]), 0.0f);
                float ayz = fmaf(ay, ay, az * az);
                if (ayz >= dmax) continue;
                int step = face ? 1 : (2 * r);
                for (int dx = -r; dx <= r; dx += step) {
                    int ccx = cx + dx;
                    if (ccx < 0 || ccx >= G) continue;
                    float ax = fmaxf(fmaxf(bx[ccx] - qx, qx - bx[ccx + 1]), 0.0f);
                    float dmin = fmaf(ax, ax, ayz);
                    if (dmin >= dmax) continue;
                    int2 se = g_cell2[(ccz * G + ccy) * G + ccx];
                    for (int j = se.x; j < se.y; j++) {
                        float4 p = g_pts[j];
                        float ddx = p.x - qx, ddy = p.y - qy, ddz = p.z - qz;
                        float d = fmaf(ddx, ddx, fmaf(ddy, ddy, ddz * ddz));
                        if (d < dmax && j != s) {
                            bd[imax] = d;
                            bj[imax] = j;
                            dmax = bd[0]; imax = 0;
#pragma unroll
                            for (int t = 1; t < KNN; t++)
                                if (bd[t] > dmax) { dmax = bd[t]; imax = t; }
                        }
                    }
                }
            }
        }
        float f = 1e30f;
        if (cx - r > 0)      f = fminf(f, qx - bx[cx - r]);
        if (cx + r + 1 < G)  f = fminf(f, bx[cx + r + 1] - qx);
        if (cy - r > 0)      f = fminf(f, qy - bx[cy - r]);
        if (cy + r + 1 < G)  f = fminf(f, bx[cy + r + 1] - qy);
        if (cz - r > 0)      f = fminf(f, qz - bx[cz - r]);
        if (cz + r + 1 < G)  f = fminf(f, bx[cz + r + 1] - qz);
        if (f * f >= dmax) break;
    }

    float sx = 0, sy = 0, sz = 0, sxx = 0, syy = 0, szz = 0;
#pragma unroll
    for (int r = 0; r < KNN; r++) {
        int slot = bj[r];
        g_knn[s * KNN + r] = slot;           // SLOT index
        float4 p = g_pts[slot];
        float rx = p.x - qx, ry = p.y - qy, rz = p.z - qz;
        sx += rx; sy += ry; sz += rz;
        sxx = fmaf(rx, rx, sxx); syy = fmaf(ry, ry, syy); szz = fmaf(rz, rz, szz);
    }
    const float inv = 1.0f / (float)KNN;
    float mx = sx * inv, my = sy * inv, mz = sz * inv;
    g_rel[s * 6 + 0] = mx;
    g_rel[s * 6 + 1] = my;
    g_rel[s * 6 + 2] = mz;
    g_rel[s * 6 + 3] = sqrtf(fmaxf(sxx * inv - mx * mx, 0.0f));
    g_rel[s * 6 + 4] = sqrtf(fmaxf(syy * inv - my * my, 0.0f));
    g_rel[s * 6 + 5] = sqrtf(fmaxf(szz * inv - mz * mz, 0.0f));
}

// ============================================================
// GEMM device body: 64m x 128n tile, 256 threads,
// 2 m-warps x 4 n-warps, warp m32xn32; A fragments via
// ldmatrix.x4 (conflict-free: bank = 4*row mod 32);
// swizzled B double-buffer.
// ============================================================
__device__ __forceinline__ void gemm_device(int m0, int n0, const u32* __restrict__ wp,
                                            float* __restrict__ Zout, u32* smem) {
    u32* As = smem;                          // [64][ASTRIDE]
    u32* Bs = smem + 64 * ASTRIDE;           // [2][BCH]
    int tid = threadIdx.x;

    const uint4* hh = reinterpret_cast<const uint4*>(g_hp_hi);  // 24 uint4/row
    const uint4* hl = reinterpret_cast<const uint4*>(g_hp_lo);
    for (int i = tid; i < 64 * 48; i += 256) {
        int row = i / 48, c4 = i % 48;
        uint4 v = (c4 < 24) ? hh[(m0 + row) * 24 + c4]
                            : hl[(m0 + row) * 24 + (c4 - 24)];
        *reinterpret_cast<uint4*>(&As[row * ASTRIDE + c4 * 4]) = v;
    }

    int wid = tid >> 5, lane = tid & 31;
    int mw = wid & 1, nw = wid >> 1;
    int r = lane >> 2, q = lane & 3;

    int brow = tid >> 5;
    int bc4  = lane * 4;
    const u32* bsrc = wp + (size_t)brow * ZN + n0 + bc4;
    int bdst = brow * BN + (bc4 ^ (brow * 8));

    int off0[4], off1[4];
#pragma unroll
    for (int nt = 0; nt < 4; nt++) {
        int nc = nw * 32 + nt * 8 + r;
        off0[nt] = bsw(q, nc);
        off1[nt] = bsw(q + 4, nc);
    }

    // ldmatrix lane base: matrices (rows0-7,acol),(rows8-15,acol),
    // (rows0-7,acol+4),(rows8-15,acol+4) == a0,a1,a2,a3
    u32 abase = (u32)__cvta_generic_to_shared(As)
              + ((mw * 32 + (lane & 15)) * ASTRIDE + ((lane >> 4) << 2)) * 4;

    float c0[2][4], c1[2][4], c2[2][4], c3[2][4];
#pragma unroll
    for (int mt = 0; mt < 2; mt++)
#pragma unroll
        for (int t = 0; t < 4; t++) {
            c0[mt][t] = 0; c1[mt][t] = 0; c2[mt][t] = 0; c3[mt][t] = 0;
        }

    uint4 pref = *reinterpret_cast<const uint4*>(bsrc);
    __syncthreads();

#pragma unroll 2
    for (int ks = 0; ks < KS; ks++) {
        u32* bbuf = Bs + (ks & 1) * BCH;
        *reinterpret_cast<uint4*>(&bbuf[bdst]) = pref;
        __syncthreads();
        if (ks + 1 < KS)
            pref = *reinterpret_cast<const uint4*>(bsrc + (size_t)(ks + 1) * 8 * ZN);

        int acol = (ks < 24) ? (((ks >= 12) ? ks - 12 : ks) * 8)
                             : (96 + (ks - 24) * 8);
        u32 bf0[4], bf1[4];
#pragma unroll
        for (int nt = 0; nt < 4; nt++) {
            bf0[nt] = bbuf[off0[nt]];
            bf1[nt] = bbuf[off1[nt]];
        }
#pragma unroll
        for (int mt = 0; mt < 2; mt++) {
            u32 a0, a1, a2, a3;
            asm volatile(
                "ldmatrix.sync.aligned.m8n8.x4.shared.b16 {%0,%1,%2,%3}, [%4];"
                : "=r"(a0), "=r"(a1), "=r"(a2), "=r"(a3)
                : "r"(abase + (u32)(acol * 4 + mt * 16 * ASTRIDE * 4)));
#pragma unroll
            for (int nt = 0; nt < 4; nt++) {
                asm volatile(
                    "mma.sync.aligned.m16n8k16.row.col.f32.bf16.bf16.f32 "
                    "{%0,%1,%2,%3}, {%4,%5,%6,%7}, {%8,%9}, {%0,%1,%2,%3};"
                    : "+f"(c0[mt][nt]), "+f"(c1[mt][nt]), "+f"(c2[mt][nt]), "+f"(c3[mt][nt])
                    : "r"(a0), "r"(a1), "r"(a2), "r"(a3), "r"(bf0[nt]), "r"(bf1[nt]));
            }
        }
    }

#pragma unroll
    for (int mt = 0; mt < 2; mt++) {
#pragma unroll
        for (int nt = 0; nt < 4; nt++) {
            int row = m0 + mw * 32 + mt * 16 + r;
            int col = n0 + nw * 32 + nt * 8 + q * 2;
            *reinterpret_cast<float2*>(&Zout[(size_t)row * ZN + col]) =
                make_float2(c0[mt][nt], c1[mt][nt]);
            *reinterpret_cast<float2*>(&Zout[(size_t)(row + 8) * ZN + col]) =
                make_float2(c2[mt][nt], c3[mt][nt]);
        }
    }
}

// ============================================================
// Fused kernel: blocks [0,KNB) run kNN; the rest run GEMM-0.
// ============================================================
__global__ __launch_bounds__(256) void fused0_kernel(const u32* __restrict__ wp,
                                                     float* __restrict__ Zout, int n) {
    extern __shared__ u32 smem[];
    if (blockIdx.x < KNB) {
        __shared__ float bx[G + 1];
        if (threadIdx.x <= G) bx[threadIdx.x] = g_bx[threadIdx.x];
        __syncthreads();
        knn_device(blockIdx.x * 256 + threadIdx.x, n, bx);
    } else {
        int bid = blockIdx.x - KNB;
        gemm_device((bid & 511) * 64, (bid >> 9) * BN, wp, Zout, smem);
    }
}

__global__ __launch_bounds__(256) void gemm_kernel(const u32* __restrict__ wp,
                                                   float* __restrict__ Zout) {
    extern __shared__ u32 smem[];
    gemm_device(blockIdx.x * 64, blockIdx.y * BN, wp, Zout, smem);
}

// ============================================================
// Projection (slot space): reads g_pts, writes g_hp by slot.
// ============================================================
__global__ __launch_bounds__(192) void proj_kernel(const float* __restrict__ B0,
                                                   const float* __restrict__ B1,
                                                   const float* __restrict__ B2,
                                                   const float* __restrict__ Wp) {
    __shared__ float pe[TPL][52];
    int c    = threadIdx.x;
    int base = blockIdx.x * TPL;

    if (c < TPL) {
        float4 pt = g_pts[base + c];
        float x0 = pt.x, x1 = pt.y, x2 = pt.z;
        const float* Bs[3] = { B0, B1, B2 };
#pragma unroll
        for (int b = 0; b < 3; b++) {
            const float* B = Bs[b];
#pragma unroll
            for (int j = 0; j < 8; j++) {
                float v = fmaf(x0, B[j], fmaf(x1, B[8 + j], x2 * B[16 + j]));
                float sn, cs;
                sincosf(v, &sn, &cs);
                pe[c][b * 16 + j]     = sn;
                pe[c][b * 16 + 8 + j] = cs;
            }
        }
        pe[c][48] = x0; pe[c][49] = x1; pe[c][50] = x2;
    }
    __syncthreads();

    float acc[TPL];
    float zb = g_zwpb[c];
#pragma unroll
    for (int p = 0; p < TPL; p++) acc[p] = zb;
    for (int k = 0; k < 51; k++) {
        float w = Wp[k * WIDTH + c];
#pragma unroll
        for (int p = 0; p < TPL; p++)
            acc[p] = fmaf(pe[p][k], w, acc[p]);
    }
#pragma unroll
    for (int p = 0; p < TPL; p++) {
        float v = acc[p];
        float h = v / (1.0f + expf(-v));
        u16 hi = f2bf(h);
        g_hp_hi[(base + p) * WIDTH + c] = hi;
        g_hp_lo[(base + p) * WIDTH + c] = f2bf(h - bf2f(hi));
    }
}

// ============================================================
// Epilogue (slot space): h' = FiLM(silu(Z1 + mean Z2[nbr] + rel@W3 + b))
// flags: bit0 = write g_hf (last layer), bit1 = write g_hp (non-last)
// ============================================================
__global__ __launch_bounds__(192) void epi_kernel(const float* __restrict__ Z,
                                                  const float* __restrict__ W3,  // [6][192]
                                                  const float* __restrict__ bl,
                                                  const float* __restrict__ gamma,
                                                  const float* __restrict__ beta,
                                                  int flags) {
    __shared__ int   nidx[TPL * KNN];     // 384
    __shared__ float w3s[6 * WIDTH];
    __shared__ float rels[TPL][6];
    int c    = threadIdx.x;
    int base = blockIdx.x * TPL;

    nidx[c]       = g_knn[base * KNN + c];
    nidx[c + 192] = g_knn[base * KNN + 192 + c];
#pragma unroll
    for (int k = 0; k < 6; k++)
        w3s[k * WIDTH + c] = W3[k * WIDTH + c];
    rels[c / 6][c % 6] = g_rel[base * 6 + c];     // 192 = 32*6
    __syncthreads();

    float bc = bl[c], gc = gamma[c], bt = beta[c];
    float w30 = w3s[c],             w31 = w3s[WIDTH + c],     w32 = w3s[2 * WIDTH + c];
    float w33 = w3s[3 * WIDTH + c], w34 = w3s[4 * WIDTH + c], w35 = w3s[5 * WIDTH + c];
    bool whf = (flags & 1) != 0;
    bool whp = (flags & 2) != 0;

#pragma unroll 2
    for (int p = 0; p < TPL; p++) {
        int m = base + p;
        float z = Z[(size_t)m * ZN + c];
        float s = 0.0f;
#pragma unroll
        for (int j = 0; j < KNN; j++)
            s += Z[(size_t)nidx[p * KNN + j] * ZN + WIDTH + c];
        float rc = rels[p][0] * w30;
        rc = fmaf(rels[p][1], w31, rc);
        rc = fmaf(rels[p][2], w32, rc);
        rc = fmaf(rels[p][3], w33, rc);
        rc = fmaf(rels[p][4], w34, rc);
        rc = fmaf(rels[p][5], w35, rc);
        float v  = z + s * (1.0f / (float)KNN) + rc + bc;
        float sv = v / (1.0f + expf(-v));
        float o  = fmaf(sv, gc, bt);
        if (whf)
            g_hf[m * WIDTH + c] = o;
        if (whp) {
            u16 hi = f2bf(o);
            g_hp_hi[m * WIDTH + c] = hi;
            g_hp_lo[m * WIDTH + c] = f2bf(o - bf2f(hi));
        }
    }
}

// ============================================================
// Output: out[orig] = (h[slot] @ Wout + bout) * 0.01
// ============================================================
__global__ __launch_bounds__(256) void out_kernel(const float* __restrict__ h,
                                                  const float* __restrict__ Wout,
                                                  const float* __restrict__ bout,
                                                  float* __restrict__ out, int n) {
    int s    = (blockIdx.x * blockDim.x + threadIdx.x) >> 5;
    int lane = threadIdx.x & 31;
    if (s >= n) return;
    float o0 = 0, o1 = 0, o2 = 0;
    for (int c = lane; c < WIDTH; c += 32) {
        float hv = h[s * WIDTH + c];
        o0 = fmaf(hv, Wout[c * 3 + 0], o0);
        o1 = fmaf(hv, Wout[c * 3 + 1], o1);
        o2 = fmaf(hv, Wout[c * 3 + 2], o2);
    }
#pragma unroll
    for (int off = 16; off; off >>= 1) {
        o0 += __shfl_down_sync(0xffffffffu, o0, off);
        o1 += __shfl_down_sync(0xffffffffu, o1, off);
        o2 += __shfl_down_sync(0xffffffffu, o2, off);
    }
    if (lane == 0) {
        int qi = __float_as_int(g_pts[s].w);
        out[qi * 3 + 0] = (o0 + bout[0]) * 0.01f;
        out[qi * 3 + 1] = (o1 + bout[1]) * 0.01f;
        out[qi * 3 + 2] = (o2 + bout[2]) * 0.01f;
    }
}

// ============================================================
extern "C" void kernel_launch(void* const* d_in, const int* in_sizes, int n_in,
                              void* d_out, int out_size) {
    const float* x    = (const float*)d_in[0];
    const float* z    = (const float*)d_in[1];
    const float* B0   = (const float*)d_in[2];
    const float* B1   = (const float*)d_in[3];
    const float* B2   = (const float*)d_in[4];
    const float* Wp   = (const float*)d_in[5];
    const float* bp   = (const float*)d_in[6];
    const float* Wl   = (const float*)d_in[7];
    const float* bl   = (const float*)d_in[8];
    const float* Wg   = (const float*)d_in[9];
    const float* bg   = (const float*)d_in[10];
    const float* Wb   = (const float*)d_in[11];
    const float* Wbb  = (const float*)d_in[12];
    const float* Wout = (const float*)d_in[13];
    const float* bout = (const float*)d_in[14];
    float* out = (float*)d_out;

    int n = in_sizes[0] / 3;   // 32768

    float *Zp, *hf, *gma, *bta;
    u32* wp;
    cudaGetSymbolAddress((void**)&Zp,  g_Z);
    cudaGetSymbolAddress((void**)&hf,  g_hf);
    cudaGetSymbolAddress((void**)&gma, g_gamma);
    cudaGetSymbolAddress((void**)&bta, g_beta);
    cudaGetSymbolAddress((void**)&wp,  g_wp);

    const int smem_gemm = (64 * ASTRIDE + 2 * BCH) * (int)sizeof(u32);  // 58368
    cudaFuncSetAttribute(gemm_kernel,   cudaFuncAttributeMaxDynamicSharedMemorySize, smem_gemm);
    cudaFuncSetAttribute(fused0_kernel, cudaFuncAttributeMaxDynamicSharedMemorySize, smem_gemm);

    setup_kernel<<<1, WIDTH>>>(z, Wp, bp, Wg, bg, Wb, Wbb);            // 0
    wtrans_kernel<<<dim3(288, NLAYERS), ZN>>>(Wl);                     // 1
    hist_kernel<<<n / 256, 256>>>(x, n);                               // 2
    scan_kernel<<<1, 1024>>>();                                        // 3 (profiled)
    scatter_kernel<<<n / 256, 256>>>(x, n);                            // 4
    proj_kernel<<<n / TPL, WIDTH>>>(B0, B1, B2, Wp);                   // 5
    fused0_kernel<<<KNB + (n / 64) * (ZN / BN), 256, smem_gemm>>>(wp, Zp, n);  // 6
    epi_kernel<<<n / TPL, WIDTH>>>(Zp, Wl + 384 * WIDTH, bl, gma, bta, 2);     // 7

    for (int li = 1; li < NLAYERS; li++) {
        gemm_kernel<<<dim3(n / 64, ZN / BN), 256, smem_gemm>>>(wp + (size_t)li * 288 * ZN, Zp);
        epi_kernel<<<n / TPL, WIDTH>>>(Zp,
            Wl + (size_t)li * MIXDIM * WIDTH + 384 * WIDTH,
            bl + li * WIDTH, gma + li * WIDTH, bta + li * WIDTH,
            (li == NLAYERS - 1) ? 1 : 2);
    }

    out_kernel<<<(n * 32 + 255) / 256, 256>>>(hf, Wout, bout, out, n);
}

// round 16
// speedup vs baseline: 1.3767x; 1.0162x over previous
#include <cuda_runtime.h>
#include <math.h>

#define NPTS    32768
#define WIDTH   192
#define COND    64
#define KNN     12
#define NLAYERS 4
#define MIXDIM  390
#define TPL     32            // points per block (proj)

// ---- quantile grid for kNN ----
#define G       16
#define NCELLS  (G*G*G)          // 4096
#define KNB     (NPTS / 256)     // 128 knn blocks in fused kernel

// ---- GEMM config: Z(N x 384) = A'(N x 576 bf16) @ B'(576 x 384 bf16)
#define ZN      384
#define KS      36               // k-steps of 16 (576/16)
#define NCH     (KS / 2)         // 18 double-chunks
#define ASTRIDE 196              // u32 stride for A smem rows (bank-safe)
#define BN      128              // block n-tile
#define BCH2    (16 * BN)        // u32 per B chunk (16 k-pair rows x 128 cols)

typedef unsigned int  u32;
typedef unsigned short u16;

// ---- scratch (static device allocations; no cudaMalloc allowed) ----
__device__ float  g_Z[NPTS * ZN];            // 50 MB (slot space)
__device__ float  g_hf[NPTS * WIDTH];        // fp32 h (slot space)
__device__ u16    g_hp_hi[NPTS * WIDTH];     // bf16 hi of h (slot space)
__device__ u16    g_hp_lo[NPTS * WIDTH];     // bf16 lo of h (slot space)
__device__ u32    g_wp[NLAYERS * 288 * ZN];  // packed bf16-pair weights
__device__ int    g_knn[NPTS * KNN];         // neighbor SLOTS (slot space)
__device__ float  g_rel[NPTS * 6];           // (slot space)
__device__ float  g_zwpb[WIDTH];
__device__ float  g_gamma[NLAYERS * WIDTH];
__device__ float  g_beta[NLAYERS * WIDTH];

__device__ float  g_bx[G + 1];
__device__ int    g_cnt[NCELLS];
__device__ int    g_cursor[NCELLS];
__device__ int2   g_cell2[NCELLS];
__device__ float4 g_pts[NPTS];               // sorted (x,y,z, orig-idx-as-bits)

// ---- bf16 helpers (hand-rolled, RNE) ----
__device__ __forceinline__ u16 f2bf(float f) {
    u32 b = __float_as_uint(f);
    return (u16)((b + 0x7FFFu + ((b >> 16) & 1u)) >> 16);
}
__device__ __forceinline__ float bf2f(u16 u) {
    return __uint_as_float(((u32)u) << 16);
}

__device__ __forceinline__ int cell_of(float v, const float* bx) {
    int lo = 0;
    if (v >= bx[8])      lo = 8;
    if (v >= bx[lo + 4]) lo += 4;
    if (v >= bx[lo + 2]) lo += 2;
    if (v >= bx[lo + 1]) lo += 1;
    return lo;
}

// B smem swizzle: row 0..15 (k-pair), col 0..127 (n) -> conflict-free
__device__ __forceinline__ int bsw(int row, int col) {
    return row * BN + (col ^ ((row * 8) & 127));
}

// ============================================================
// Setup: zero grid counters + z-dependent constants + quantiles
// ============================================================
__global__ void setup_kernel(const float* __restrict__ z,
                             const float* __restrict__ Wp, const float* __restrict__ bp,
                             const float* __restrict__ Wg, const float* __restrict__ bg,
                             const float* __restrict__ Wb, const float* __restrict__ bb) {
    int c = threadIdx.x;
    for (int i = c; i < NCELLS; i += blockDim.x) g_cnt[i] = 0;
    if (c <= G) {
        g_bx[c] = (c == 0) ? -1e9f : ((c == G) ? 1e9f
                  : normcdfinvf((float)c / (float)G));
    }
    if (c >= WIDTH) return;
    float s = bp[c];
    for (int k = 0; k < COND; k++)
        s = fmaf(z[k], Wp[(51 + k) * WIDTH + c], s);
    g_zwpb[c] = s;
    for (int li = 0; li < NLAYERS; li++) {
        const float* wg = Wg + li * COND * WIDTH;
        const float* wb = Wb + li * COND * WIDTH;
        float g = bg[li * WIDTH + c];
        float b = bb[li * WIDTH + c];
        for (int k = 0; k < COND; k++) {
            float zk = z[k];
            g = fmaf(zk, wg[k * WIDTH + c], g);
            b = fmaf(zk, wb[k * WIDTH + c], b);
        }
        g_gamma[li * WIDTH + c] = g;
        g_beta[li * WIDTH + c]  = b;
    }
}

// ============================================================
// Weight pack: B' = [Bhi ; Blo ; Bhi] (576 x 384) as bf16 pairs.
// ============================================================
__global__ void wtrans_kernel(const float* __restrict__ Wl) {
    int i  = blockIdx.x;          // u32 row 0..287
    int li = blockIdx.y;
    int n  = threadIdx.x;         // 0..383
    int r  = i / 96;              // region: 0=hi, 1=lo, 2=hi
    int kb = 2 * i - r * 192;     // mix-k base (0..190)
    const float* W = Wl + (size_t)li * MIXDIM * WIDTH;
    int col  = (n < 192) ? n : (n - 192);
    int roff = (n < 192) ? 0 : 192;
    float f0 = W[(roff + kb)     * WIDTH + col];
    float f1 = W[(roff + kb + 1) * WIDTH + col];
    u16 v0, v1;
    if (r == 1) {
        u16 h0 = f2bf(f0), h1 = f2bf(f1);
        v0 = f2bf(f0 - bf2f(h0));
        v1 = f2bf(f1 - bf2f(h1));
    } else {
        v0 = f2bf(f0);
        v1 = f2bf(f1);
    }
    g_wp[(li * 288 + i) * ZN + n] = ((u32)v1 << 16) | (u32)v0;
}

// ============================================================
// Grid build: histogram -> single-block scan -> scatter
// ============================================================
__global__ void hist_kernel(const float* __restrict__ x, int n) {
    int i = blockIdx.x * blockDim.x + threadIdx.x;
    if (i >= n) return;
    const float* bx = g_bx;
    int cx = cell_of(x[i * 3 + 0], bx);
    int cy = cell_of(x[i * 3 + 1], bx);
    int cz = cell_of(x[i * 3 + 2], bx);
    atomicAdd(&g_cnt[(cz * G + cy) * G + cx], 1);
}

__global__ void scan_kernel() {
    __shared__ int sh[1024];
    int t = threadIdx.x;
    int4 v = *reinterpret_cast<const int4*>(&g_cnt[t * 4]);
    int s = v.x + v.y + v.z + v.w;
    sh[t] = s;
    __syncthreads();
    for (int off = 1; off < 1024; off <<= 1) {
        int u = (t >= off) ? sh[t - off] : 0;
        __syncthreads();
        sh[t] += u;
        __syncthreads();
    }
    int ex = sh[t] - s;
    int st0 = ex, st1 = st0 + v.x, st2 = st1 + v.y, st3 = st2 + v.z;
    g_cursor[t * 4 + 0] = st0;  g_cell2[t * 4 + 0] = make_int2(st0, st1);
    g_cursor[t * 4 + 1] = st1;  g_cell2[t * 4 + 1] = make_int2(st1, st2);
    g_cursor[t * 4 + 2] = st2;  g_cell2[t * 4 + 2] = make_int2(st2, st3);
    g_cursor[t * 4 + 3] = st3;  g_cell2[t * 4 + 3] = make_int2(st3, st3 + v.w);
}

__global__ void scatter_kernel(const float* __restrict__ x, int n) {
    int i = blockIdx.x * blockDim.x + threadIdx.x;
    if (i >= n) return;
    const float* bx = g_bx;
    float px = x[i * 3 + 0], py = x[i * 3 + 1], pz = x[i * 3 + 2];
    int cx = cell_of(px, bx), cy = cell_of(py, bx), cz = cell_of(pz, bx);
    int cell = (cz * G + cy) * G + cx;
    int slot = atomicAdd(&g_cursor[cell], 1);
    g_pts[slot] = make_float4(px, py, pz, __int_as_float(i));
}

// ============================================================
// kNN device body: one thread per sorted point; outputs in
// SLOT space (g_knn holds neighbor slots, g_rel by slot).
// ============================================================
__device__ __noinline__ void knn_device(int s, int n, const float* bx) {
    if (s >= n) return;
    float4 me = g_pts[s];
    float qx = me.x, qy = me.y, qz = me.z;
    int cx = cell_of(qx, bx), cy = cell_of(qy, bx), cz = cell_of(qz, bx);

    float bd[KNN];
    int   bj[KNN];
#pragma unroll
    for (int r = 0; r < KNN; r++) { bd[r] = 1e30f; bj[r] = 0; }
    float dmax = 1e30f;
    int   imax = 0;

    for (int r = 0; r < G; r++) {
        int zlo = max(cz - r, 0), zhi = min(cz + r, G - 1);
        for (int ccz = zlo; ccz <= zhi; ccz++) {
            bool zface = (ccz == cz - r) || (ccz == cz + r);
            float az = fmaxf(fmaxf(bx[ccz] - qz, qz - bx[ccz + 1]), 0.0f);
            int ylo = max(cy - r, 0), yhi = min(cy + r, G - 1);
            for (int ccy = ylo; ccy <= yhi; ccy++) {
                bool face = zface || (ccy == cy - r) || (ccy == cy + r);
                float ay = fmaxf(fmaxf(bx[ccy] - qy, qy - bx[ccy + 1]), 0.0f);
                float ayz = fmaf(ay, ay, az * az);
                if (ayz >= dmax) continue;
                int step = face ? 1 : (2 * r);
                for (int dx = -r; dx <= r; dx += step) {
                    int ccx = cx + dx;
                    if (ccx < 0 || ccx >= G) continue;
                    float ax = fmaxf(fmaxf(bx[ccx] - qx, qx - bx[ccx + 1]), 0.0f);
                    float dmin = fmaf(ax, ax, ayz);
                    if (dmin >= dmax) continue;
                    int2 se = g_cell2[(ccz * G + ccy) * G + ccx];
                    for (int j = se.x; j < se.y; j++) {
                        float4 p = g_pts[j];
                        float ddx = p.x - qx, ddy = p.y - qy, ddz = p.z - qz;
                        float d = fmaf(ddx, ddx, fmaf(ddy, ddy, ddz * ddz));
                        if (d < dmax && j != s) {
                            bd[imax] = d;
                            bj[imax] = j;
                            dmax = bd[0]; imax = 0;
#pragma unroll
                            for (int t = 1; t < KNN; t++)
                                if (bd[t] > dmax) { dmax = bd[t]; imax = t; }
                        }
                    }
                }
            }
        }
        float f = 1e30f;
        if (cx - r > 0)      f = fminf(f, qx - bx[cx - r]);
        if (cx + r + 1 < G)  f = fminf(f, bx[cx + r + 1] - qx);
        if (cy - r > 0)      f = fminf(f, qy - bx[cy - r]);
        if (cy + r + 1 < G)  f = fminf(f, bx[cy + r + 1] - qy);
        if (cz - r > 0)      f = fminf(f, qz - bx[cz - r]);
        if (cz + r + 1 < G)  f = fminf(f, bx[cz + r + 1] - qz);
        if (f * f >= dmax) break;
    }

    float sx = 0, sy = 0, sz = 0, sxx = 0, syy = 0, szz = 0;
#pragma unroll
    for (int r = 0; r < KNN; r++) {
        int slot = bj[r];
        g_knn[s * KNN + r] = slot;           // SLOT index
        float4 p = g_pts[slot];
        float rx = p.x - qx, ry = p.y - qy, rz = p.z - qz;
        sx += rx; sy += ry; sz += rz;
        sxx = fmaf(rx, rx, sxx); syy = fmaf(ry, ry, syy); szz = fmaf(rz, rz, szz);
    }
    const float inv = 1.0f / (float)KNN;
    float mx = sx * inv, my = sy * inv, mz = sz * inv;
    g_rel[s * 6 + 0] = mx;
    g_rel[s * 6 + 1] = my;
    g_rel[s * 6 + 2] = mz;
    g_rel[s * 6 + 3] = sqrtf(fmaxf(sxx * inv - mx * mx, 0.0f));
    g_rel[s * 6 + 4] = sqrtf(fmaxf(syy * inv - my * my, 0.0f));
    g_rel[s * 6 + 5] = sqrtf(fmaxf(szz * inv - mz * mz, 0.0f));
}

// ============================================================
// GEMM device body: 64m x 128n tile, 256 threads,
// 2 m-warps x 4 n-warps, warp m32xn32; ldmatrix A fragments;
// B staged 2 k-steps per chunk (ONE barrier per 2 k-steps),
// double-buffered, swizzled conflict-free.
// ============================================================
__device__ __forceinline__ void gemm_device(int m0, int n0, const u32* __restrict__ wp,
                                            float* __restrict__ Zout, u32* smem) {
    u32* As = smem;                          // [64][ASTRIDE]
    u32* Bs = smem + 64 * ASTRIDE;           // [2][BCH2]
    int tid = threadIdx.x;

    const uint4* hh = reinterpret_cast<const uint4*>(g_hp_hi);  // 24 uint4/row
    const uint4* hl = reinterpret_cast<const uint4*>(g_hp_lo);
    for (int i = tid; i < 64 * 48; i += 256) {
        int row = i / 48, c4 = i % 48;
        uint4 v = (c4 < 24) ? hh[(m0 + row) * 24 + c4]
                            : hl[(m0 + row) * 24 + (c4 - 24)];
        *reinterpret_cast<uint4*>(&As[row * ASTRIDE + c4 * 4]) = v;
    }

    int wid = tid >> 5, lane = tid & 31;
    int mw = wid & 1, nw = wid >> 1;
    int r = lane >> 2, q = lane & 3;

    int brow = tid >> 5;                      // 0..7
    int bc4  = lane * 4;                      // 0..124
    const u32* bsrc0 = wp + (size_t)brow * ZN + n0 + bc4;        // rows brow
    const u32* bsrc1 = bsrc0 + 8 * (size_t)ZN;                   // rows brow+8
    int bdst0 = bsw(brow, bc4);
    int bdst1 = bsw(brow + 8, bc4);

    // fragment-read smem offsets for both k-step parities
    int off0[2][4], off1[2][4];
#pragma unroll
    for (int p = 0; p < 2; p++)
#pragma unroll
        for (int nt = 0; nt < 4; nt++) {
            int nc = nw * 32 + nt * 8 + r;
            off0[p][nt] = bsw(q + 8 * p, nc);
            off1[p][nt] = bsw(q + 4 + 8 * p, nc);
        }

    // ldmatrix lane base
    u32 abase = (u32)__cvta_generic_to_shared(As)
              + ((mw * 32 + (lane & 15)) * ASTRIDE + ((lane >> 4) << 2)) * 4;

    float c0[2][4], c1[2][4], c2[2][4], c3[2][4];
#pragma unroll
    for (int mt = 0; mt < 2; mt++)
#pragma unroll
        for (int t = 0; t < 4; t++) {
            c0[mt][t] = 0; c1[mt][t] = 0; c2[mt][t] = 0; c3[mt][t] = 0;
        }

    uint4 pref0 = *reinterpret_cast<const uint4*>(bsrc0);
    uint4 pref1 = *reinterpret_cast<const uint4*>(bsrc1);
    __syncthreads();                           // A staging done

#pragma unroll 2
    for (int ch = 0; ch < NCH; ch++) {
        u32* bbuf = Bs + (ch & 1) * BCH2;
        *reinterpret_cast<uint4*>(&bbuf[bdst0]) = pref0;
        *reinterpret_cast<uint4*>(&bbuf[bdst1]) = pref1;
        __syncthreads();
        if (ch + 1 < NCH) {
            pref0 = *reinterpret_cast<const uint4*>(bsrc0 + (size_t)(ch + 1) * 16 * ZN);
            pref1 = *reinterpret_cast<const uint4*>(bsrc1 + (size_t)(ch + 1) * 16 * ZN);
        }
#pragma unroll
        for (int p = 0; p < 2; p++) {
            int ks = ch * 2 + p;
            int acol = (ks < 24) ? (((ks >= 12) ? ks - 12 : ks) * 8)
                                 : (96 + (ks - 24) * 8);
            u32 bf0[4], bf1[4];
#pragma unroll
            for (int nt = 0; nt < 4; nt++) {
                bf0[nt] = bbuf[off0[p][nt]];
                bf1[nt] = bbuf[off1[p][nt]];
            }
#pragma unroll
            for (int mt = 0; mt < 2; mt++) {
                u32 a0, a1, a2, a3;
                asm volatile(
                    "ldmatrix.sync.aligned.m8n8.x4.shared.b16 {%0,%1,%2,%3}, [%4];"
                    : "=r"(a0), "=r"(a1), "=r"(a2), "=r"(a3)
                    : "r"(abase + (u32)(acol * 4 + mt * 16 * ASTRIDE * 4)));
#pragma unroll
                for (int nt = 0; nt < 4; nt++) {
                    asm volatile(
                        "mma.sync.aligned.m16n8k16.row.col.f32.bf16.bf16.f32 "
                        "{%0,%1,%2,%3}, {%4,%5,%6,%7}, {%8,%9}, {%0,%1,%2,%3};"
                        : "+f"(c0[mt][nt]), "+f"(c1[mt][nt]), "+f"(c2[mt][nt]), "+f"(c3[mt][nt])
                        : "r"(a0), "r"(a1), "r"(a2), "r"(a3), "r"(bf0[nt]), "r"(bf1[nt]));
                }
            }
        }
    }

#pragma unroll
    for (int mt = 0; mt < 2; mt++) {
#pragma unroll
        for (int nt = 0; nt < 4; nt++) {
            int row = m0 + mw * 32 + mt * 16 + r;
            int col = n0 + nw * 32 + nt * 8 + q * 2;
            *reinterpret_cast<float2*>(&Zout[(size_t)row * ZN + col]) =
                make_float2(c0[mt][nt], c1[mt][nt]);
            *reinterpret_cast<float2*>(&Zout[(size_t)(row + 8) * ZN + col]) =
                make_float2(c2[mt][nt], c3[mt][nt]);
        }
    }
}

// ============================================================
// Fused kernel: blocks [0,KNB) run kNN; the rest run GEMM-0.
// ============================================================
__global__ __launch_bounds__(256) void fused0_kernel(const u32* __restrict__ wp,
                                                     float* __restrict__ Zout, int n) {
    extern __shared__ u32 smem[];
    if (blockIdx.x < KNB) {
        __shared__ float bx[G + 1];
        if (threadIdx.x <= G) bx[threadIdx.x] = g_bx[threadIdx.x];
        __syncthreads();
        knn_device(blockIdx.x * 256 + threadIdx.x, n, bx);
    } else {
        int bid = blockIdx.x - KNB;
        gemm_device((bid & 511) * 64, (bid >> 9) * BN, wp, Zout, smem);
    }
}

__global__ __launch_bounds__(256) void gemm_kernel(const u32* __restrict__ wp,
                                                   float* __restrict__ Zout) {
    extern __shared__ u32 smem[];
    gemm_device(blockIdx.x * 64, blockIdx.y * BN, wp, Zout, smem);
}

// ============================================================
// Projection (slot space): reads g_pts, writes g_hp by slot.
// ============================================================
__global__ __launch_bounds__(192) void proj_kernel(const float* __restrict__ B0,
                                                   const float* __restrict__ B1,
                                                   const float* __restrict__ B2,
                                                   const float* __restrict__ Wp) {
    __shared__ float pe[TPL][52];
    int c    = threadIdx.x;
    int base = blockIdx.x * TPL;

    if (c < TPL) {
        float4 pt = g_pts[base + c];
        float x0 = pt.x, x1 = pt.y, x2 = pt.z;
        const float* Bs[3] = { B0, B1, B2 };
#pragma unroll
        for (int b = 0; b < 3; b++) {
            const float* B = Bs[b];
#pragma unroll
            for (int j = 0; j < 8; j++) {
                float v = fmaf(x0, B[j], fmaf(x1, B[8 + j], x2 * B[16 + j]));
                float sn, cs;
                sincosf(v, &sn, &cs);
                pe[c][b * 16 + j]     = sn;
                pe[c][b * 16 + 8 + j] = cs;
            }
        }
        pe[c][48] = x0; pe[c][49] = x1; pe[c][50] = x2;
    }
    __syncthreads();

    float acc[TPL];
    float zb = g_zwpb[c];
#pragma unroll
    for (int p = 0; p < TPL; p++) acc[p] = zb;
    for (int k = 0; k < 51; k++) {
        float w = Wp[k * WIDTH + c];
#pragma unroll
        for (int p = 0; p < TPL; p++)
            acc[p] = fmaf(pe[p][k], w, acc[p]);
    }
#pragma unroll
    for (int p = 0; p < TPL; p++) {
        float v = acc[p];
        float h = v / (1.0f + expf(-v));
        u16 hi = f2bf(h);
        g_hp_hi[(base + p) * WIDTH + c] = hi;
        g_hp_lo[(base + p) * WIDTH + c] = f2bf(h - bf2f(hi));
    }
}

// ============================================================
// Epilogue (slot space): h' = FiLM(silu(Z1 + mean Z2[nbr] + rel@W3 + b))
// flags: bit0 = write g_hf (last layer), bit1 = write g_hp (non-last)
// ============================================================
__global__ __launch_bounds__(192) void epi_kernel(const float* __restrict__ Z,
                                                  const float* __restrict__ W3,  // [6][192]
                                                  const float* __restrict__ bl,
                                                  const float* __restrict__ gamma,
                                                  const float* __restrict__ beta,
                                                  int flags) {
    __shared__ int   nidx[TPL * KNN];     // 384
    __shared__ float w3s[6 * WIDTH];
    __shared__ float rels[TPL][6];
    int c    = threadIdx.x;
    int base = blockIdx.x * TPL;

    nidx[c]       = g_knn[base * KNN + c];
    nidx[c + 192] = g_knn[base * KNN + 192 + c];
#pragma unroll
    for (int k = 0; k < 6; k++)
        w3s[k * WIDTH + c] = W3[k * WIDTH + c];
    rels[c / 6][c % 6] = g_rel[base * 6 + c];     // 192 = 32*6
    __syncthreads();

    float bc = bl[c], gc = gamma[c], bt = beta[c];
    float w30 = w3s[c],             w31 = w3s[WIDTH + c],     w32 = w3s[2 * WIDTH + c];
    float w33 = w3s[3 * WIDTH + c], w34 = w3s[4 * WIDTH + c], w35 = w3s[5 * WIDTH + c];
    bool whf = (flags & 1) != 0;
    bool whp = (flags & 2) != 0;

#pragma unroll 2
    for (int p = 0; p < TPL; p++) {
        int m = base + p;
        float z = Z[(size_t)m * ZN + c];
        float s = 0.0f;
#pragma unroll
        for (int j = 0; j < KNN; j++)
            s += Z[(size_t)nidx[p * KNN + j] * ZN + WIDTH + c];
        float rc = rels[p][0] * w30;
        rc = fmaf(rels[p][1], w31, rc);
        rc = fmaf(rels[p][2], w32, rc);
        rc = fmaf(rels[p][3], w33, rc);
        rc = fmaf(rels[p][4], w34, rc);
        rc = fmaf(rels[p][5], w35, rc);
        float v  = z + s * (1.0f / (float)KNN) + rc + bc;
        float sv = v / (1.0f + expf(-v));
        float o  = fmaf(sv, gc, bt);
        if (whf)
            g_hf[m * WIDTH + c] = o;
        if (whp) {
            u16 hi = f2bf(o);
            g_hp_hi[m * WIDTH + c] = hi;
            g_hp_lo[m * WIDTH + c] = f2bf(o - bf2f(hi));
        }
    }
}

// ============================================================
// Output: out[orig] = (h[slot] @ Wout + bout) * 0.01
// ============================================================
__global__ __launch_bounds__(256) void out_kernel(const float* __restrict__ h,
                                                  const float* __restrict__ Wout,
                                                  const float* __restrict__ bout,
                                                  float* __restrict__ out, int n) {
    int s    = (blockIdx.x * blockDim.x + threadIdx.x) >> 5;
    int lane = threadIdx.x & 31;
    if (s >= n) return;
    float o0 = 0, o1 = 0, o2 = 0;
    for (int c = lane; c < WIDTH; c += 32) {
        float hv = h[s * WIDTH + c];
        o0 = fmaf(hv, Wout[c * 3 + 0], o0);
        o1 = fmaf(hv, Wout[c * 3 + 1], o1);
        o2 = fmaf(hv, Wout[c * 3 + 2], o2);
    }
#pragma unroll
    for (int off = 16; off; off >>= 1) {
        o0 += __shfl_down_sync(0xffffffffu, o0, off);
        o1 += __shfl_down_sync(0xffffffffu, o1, off);
        o2 += __shfl_down_sync(0xffffffffu, o2, off);
    }
    if (lane == 0) {
        int qi = __float_as_int(g_pts[s].w);
        out[qi * 3 + 0] = (o0 + bout[0]) * 0.01f;
        out[qi * 3 + 1] = (o1 + bout[1]) * 0.01f;
        out[qi * 3 + 2] = (o2 + bout[2]) * 0.01f;
    }
}

// ============================================================
extern "C" void kernel_launch(void* const* d_in, const int* in_sizes, int n_in,
                              void* d_out, int out_size) {
    const float* x    = (const float*)d_in[0];
    const float* z    = (const float*)d_in[1];
    const float* B0   = (const float*)d_in[2];
    const float* B1   = (const float*)d_in[3];
    const float* B2   = (const float*)d_in[4];
    const float* Wp   = (const float*)d_in[5];
    const float* bp   = (const float*)d_in[6];
    const float* Wl   = (const float*)d_in[7];
    const float* bl   = (const float*)d_in[8];
    const float* Wg   = (const float*)d_in[9];
    const float* bg   = (const float*)d_in[10];
    const float* Wb   = (const float*)d_in[11];
    const float* Wbb  = (const float*)d_in[12];
    const float* Wout = (const float*)d_in[13];
    const float* bout = (const float*)d_in[14];
    float* out = (float*)d_out;

    int n = in_sizes[0] / 3;   // 32768

    float *Zp, *hf, *gma, *bta;
    u32* wp;
    cudaGetSymbolAddress((void**)&Zp,  g_Z);
    cudaGetSymbolAddress((void**)&hf,  g_hf);
    cudaGetSymbolAddress((void**)&gma, g_gamma);
    cudaGetSymbolAddress((void**)&bta, g_beta);
    cudaGetSymbolAddress((void**)&wp,  g_wp);

    const int smem_gemm = (64 * ASTRIDE + 2 * BCH2) * (int)sizeof(u32);  // 66560
    cudaFuncSetAttribute(gemm_kernel,   cudaFuncAttributeMaxDynamicSharedMemorySize, smem_gemm);
    cudaFuncSetAttribute(fused0_kernel, cudaFuncAttributeMaxDynamicSharedMemorySize, smem_gemm);

    setup_kernel<<<1, WIDTH>>>(z, Wp, bp, Wg, bg, Wb, Wbb);            // 0
    wtrans_kernel<<<dim3(288, NLAYERS), ZN>>>(Wl);                     // 1
    hist_kernel<<<n / 256, 256>>>(x, n);                               // 2
    scan_kernel<<<1, 1024>>>();                                        // 3 (profiled)
    scatter_kernel<<<n / 256, 256>>>(x, n);                            // 4
    proj_kernel<<<n / TPL, WIDTH>>>(B0, B1, B2, Wp);                   // 5
    fused0_kernel<<<KNB + (n / 64) * (ZN / BN), 256, smem_gemm>>>(wp, Zp, n);  // 6
    epi_kernel<<<n / TPL, WIDTH>>>(Zp, Wl + 384 * WIDTH, bl, gma, bta, 2);     // 7

    for (int li = 1; li < NLAYERS; li++) {
        gemm_kernel<<<dim3(n / 64, ZN / BN), 256, smem_gemm>>>(wp + (size_t)li * 288 * ZN, Zp);
        epi_kernel<<<n / TPL, WIDTH>>>(Zp,
            Wl + (size_t)li * MIXDIM * WIDTH + 384 * WIDTH,
            bl + li * WIDTH, gma + li * WIDTH, bta + li * WIDTH,
            (li == NLAYERS - 1) ? 1 : 2);
    }

    out_kernel<<<(n * 32 + 255) / 256, 256>>>(hf, Wout, bout, out, n);
}